// round 12
// baseline (speedup 1.0000x reference)
#include <cuda_runtime.h>
#include <cuda_bf16.h>
#include <math.h>
#include <stdint.h>

#define BB 32
#define TT 200
#define HH 2048
#define G4 8192   // 4*H
#define SS 256
#define TB 6400   // T*B
#define FF 20
#define NCH 64    // K chunks of 32 (pregemm/dec)
#define NC64 32   // K chunks of 64 (scan)

typedef unsigned long long ull;

// ---- cp.async ----
__device__ __forceinline__ void cpa16s(uint32_t dst, const void* src) {
    asm volatile("cp.async.cg.shared.global [%0], [%1], 16;" :: "r"(dst), "l"(src));
}
__device__ __forceinline__ void cp_commit() { asm volatile("cp.async.commit_group;"); }

__device__ __forceinline__ uint32_t smem_u32(const void* p) {
    return (uint32_t)__cvta_generic_to_shared(p);
}
__device__ __forceinline__ uint32_t sw64(uint32_t off)  { return off ^ (((off >> 7) & 7u) << 4); }
__device__ __forceinline__ uint32_t sw128(uint32_t off) { return off ^ ((off >> 3) & 0x70u); }

// ---- ldmatrix / mma.sync (baseline PTX, legal on sm_103 non-'a') ----
__device__ __forceinline__ void ldsm_x4(uint32_t* r, uint32_t addr) {
    asm volatile("ldmatrix.sync.aligned.m8n8.x4.shared.b16 {%0,%1,%2,%3}, [%4];"
                 : "=r"(r[0]), "=r"(r[1]), "=r"(r[2]), "=r"(r[3]) : "r"(addr));
}
__device__ __forceinline__ void ldsm_x2(uint32_t* r, uint32_t addr) {
    asm volatile("ldmatrix.sync.aligned.m8n8.x2.shared.b16 {%0,%1}, [%2];"
                 : "=r"(r[0]), "=r"(r[1]) : "r"(addr));
}
__device__ __forceinline__ void mma_bf16(float* c, const uint32_t* a, const uint32_t* b) {
    asm volatile(
        "mma.sync.aligned.m16n8k16.row.col.f32.bf16.bf16.f32 "
        "{%0,%1,%2,%3}, {%4,%5,%6,%7}, {%8,%9}, {%0,%1,%2,%3};"
        : "+f"(c[0]), "+f"(c[1]), "+f"(c[2]), "+f"(c[3])
        : "r"(a[0]), "r"(a[1]), "r"(a[2]), "r"(a[3]), "r"(b[0]), "r"(b[1]));
}

// ---- scratch (device globals: allocation-free rule) ----
__device__ __align__(128) float g_fused[TB * FF];
__device__ __align__(128) float g_X[TB * HH];
// g_Xh/g_Xl: first hold split X for pregemm; after the scan they hold split h (dec A)
__device__ __align__(128) __nv_bfloat16 g_Xh[(size_t)NCH * TB * 32];
__device__ __align__(128) __nv_bfloat16 g_Xl[(size_t)NCH * TB * 32];
__device__ __align__(128) __nv_bfloat16 g_Wh[(size_t)NCH * G4 * 32];
__device__ __align__(128) __nv_bfloat16 g_Wl[(size_t)NCH * G4 * 32];
__device__ __align__(128) __nv_bfloat16 g_U2h[(size_t)NC64 * G4 * 64];
__device__ __align__(128) __nv_bfloat16 g_U2l[(size_t)NC64 * G4 * 64];
__device__ __align__(128) __nv_bfloat16 g_Dh[(size_t)NCH * SS * 32];   // decW hi
__device__ __align__(128) __nv_bfloat16 g_Dl[(size_t)NCH * SS * 32];   // decW lo
__device__ __align__(128) float g_bsum[G4];
__device__ __align__(128) float g_preg[(size_t)TB * G4];
__device__ __align__(128) float g_cT[HH * BB];
__device__ __align__(128) float g_hall[(size_t)TT * HH * BB];
__device__ __align__(128) __nv_bfloat16 g_hsp[2][NC64][2][32][64];
__device__ int g_ctr[TT * 128];   // split-K arrival counters (zeroed every launch)

// ---------------- init: c transposed, h0 split ----------------
__global__ void k_init(const float* __restrict__ h0, const float* __restrict__ c0) {
    int i = blockIdx.x * blockDim.x + threadIdx.x;
    if (i < HH * BB) {
        int b = i >> 11, u = i & 2047;
        g_cT[u * BB + b] = c0[i];
        float x = h0[i];
        __nv_bfloat16 h = __float2bfloat16(x);
        __nv_bfloat16 l = __float2bfloat16(x - __bfloat162float(h));
        g_hsp[0][u >> 6][0][b][u & 63] = h;
        g_hsp[0][u >> 6][1][b][u & 63] = l;
    }
    if (i < TT * 128) g_ctr[i] = 0;
}

// ---------------- fused = [x1@m1^T+b1 , x2@m2^T+b2] ----------------
__global__ void k_fused(const float* __restrict__ in1, const float* __restrict__ in2,
                        const float* __restrict__ m1W, const float* __restrict__ m1b,
                        const float* __restrict__ m2W, const float* __restrict__ m2b) {
    int idx = blockIdx.x * blockDim.x + threadIdx.x;
    if (idx >= TB) return;
    int t = idx / BB, b = idx % BB;
    float x0 = in1[(b * TT + t) * 2 + 0];
    float x1 = in1[(b * TT + t) * 2 + 1];
    float x2 = in2[b * TT + t];
#pragma unroll
    for (int j = 0; j < 10; j++)
        g_fused[idx * FF + j] = m1W[j * 2] * x0 + m1W[j * 2 + 1] * x1 + m1b[j];
#pragma unroll
    for (int j = 0; j < 10; j++)
        g_fused[idx * FF + 10 + j] = m2W[j] * x2 + m2b[j];
}

// ---------------- expert encode ----------------
__global__ __launch_bounds__(256) void k_encode(const float* __restrict__ encW,
                                                const float* __restrict__ encb,
                                                const int* __restrict__ routers) {
    int idx = blockIdx.x;
    int t = idx / BB, b = idx % BB;
    int skill = routers[b * TT + t];
    __shared__ float sf[FF];
    if (threadIdx.x < FF) sf[threadIdx.x] = g_fused[idx * FF + threadIdx.x];
    __syncthreads();
    const float* Wbase = encW + (size_t)skill * FF * HH;
    const float* bbase = encb + skill * HH;
    for (int h = threadIdx.x; h < HH; h += 256) {
        float acc = bbase[h];
#pragma unroll
        for (int f = 0; f < FF; f++) acc += sf[f] * Wbase[f * HH + h];
        g_X[idx * HH + h] = acc;
    }
}

// ---------------- split X into chunk32-major bf16 hi/lo ----------------
__global__ __launch_bounds__(256) void k_splitX() {
    int m = blockIdx.x * 256 + threadIdx.x;
    int ch = blockIdx.y;
    const float* src = &g_X[(size_t)m * HH + ch * 32];
    union { __nv_bfloat16 b[32]; uint4 v[4]; } ph, pl;
#pragma unroll
    for (int i = 0; i < 32; i++) {
        float x = src[i];
        __nv_bfloat16 h = __float2bfloat16(x);
        ph.b[i] = h;
        pl.b[i] = __float2bfloat16(x - __bfloat162float(h));
    }
    size_t o = ((size_t)ch * TB + m) * 32;
#pragma unroll
    for (int i = 0; i < 4; i++) {
        *(uint4*)&g_Xh[o + i * 8] = ph.v[i];
        *(uint4*)&g_Xl[o + i * 8] = pl.v[i];
    }
}

// ---------------- split Wih into chunk32-major hi/lo + bias ----------------
__global__ __launch_bounds__(256) void k_splitW(const float* __restrict__ W,
                                                __nv_bfloat16* __restrict__ dh,
                                                __nv_bfloat16* __restrict__ dl,
                                                const float* __restrict__ b1,
                                                const float* __restrict__ b2,
                                                int do_bias) {
    int c = blockIdx.x * 256 + threadIdx.x;
    int ch = blockIdx.y;
    int j = (c & 3) * HH + (c >> 2);
    if (do_bias && ch == 0) g_bsum[c] = b1[j] + b2[j];
    const float* src = &W[(size_t)j * HH + ch * 32];
    union { __nv_bfloat16 b[32]; uint4 v[4]; } ph, pl;
#pragma unroll
    for (int i = 0; i < 32; i++) {
        float x = src[i];
        __nv_bfloat16 h = __float2bfloat16(x);
        ph.b[i] = h;
        pl.b[i] = __float2bfloat16(x - __bfloat162float(h));
    }
    size_t o = ((size_t)ch * G4 + c) * 32;
#pragma unroll
    for (int i = 0; i < 4; i++) {
        *(uint4*)&dh[o + i * 8] = ph.v[i];
        *(uint4*)&dl[o + i * 8] = pl.v[i];
    }
}

// ---------------- split decW (no interleave) into chunk32-major hi/lo ----------------
__global__ __launch_bounds__(256) void k_splitD(const float* __restrict__ W) {
    int s = threadIdx.x;
    int ch = blockIdx.y;
    const float* src = &W[(size_t)s * HH + ch * 32];
    union { __nv_bfloat16 b[32]; uint4 v[4]; } ph, pl;
#pragma unroll
    for (int i = 0; i < 32; i++) {
        float x = src[i];
        __nv_bfloat16 h = __float2bfloat16(x);
        ph.b[i] = h;
        pl.b[i] = __float2bfloat16(x - __bfloat162float(h));
    }
    size_t o = ((size_t)ch * SS + s) * 32;
#pragma unroll
    for (int i = 0; i < 4; i++) {
        *(uint4*)&g_Dh[o + i * 8] = ph.v[i];
        *(uint4*)&g_Dl[o + i * 8] = pl.v[i];
    }
}

// ---------------- split Whh into chunk64-major hi/lo ----------------
__global__ __launch_bounds__(256) void k_splitW64(const float* __restrict__ W) {
    int c = blockIdx.x * 256 + threadIdx.x;
    int ch = blockIdx.y;
    int j = (c & 3) * HH + (c >> 2);
    const float* src = &W[(size_t)j * HH + ch * 64];
    union { __nv_bfloat16 b[64]; uint4 v[8]; } ph, pl;
#pragma unroll
    for (int i = 0; i < 64; i++) {
        float x = src[i];
        __nv_bfloat16 h = __float2bfloat16(x);
        ph.b[i] = h;
        pl.b[i] = __float2bfloat16(x - __bfloat162float(h));
    }
    size_t o = ((size_t)ch * G4 + c) * 64;
#pragma unroll
    for (int i = 0; i < 8; i++) {
        *(uint4*)&g_U2h[o + i * 8] = ph.v[i];
        *(uint4*)&g_U2l[o + i * 8] = pl.v[i];
    }
}

// ---------------- HMMA pregemm: preg = split3(X @ Wih^T) + bias  [6400 x 8192] ----------------
__global__ __launch_bounds__(256) void k_hmma() {
    extern __shared__ char dsm[];   // 3 x 32KB
    __shared__ float sbias[128];
    int tid = threadIdx.x, wid = tid >> 5, lane = tid & 31;
    int wm = wid & 1, wn = wid >> 1;
    int m0 = blockIdx.y * 128, n0 = blockIdx.x * 128;
    uint32_t sb = smem_u32(dsm);
    if (tid < 128) sbias[tid] = g_bsum[n0 + tid];

    auto stage = [&](int ch, int buf) {
        uint32_t tb = sb + buf * 32768;
        const char* sAh = (const char*)g_Xh + ((size_t)ch * TB + m0) * 64;
        const char* sAl = (const char*)g_Xl + ((size_t)ch * TB + m0) * 64;
        const char* sBh = (const char*)g_Wh + ((size_t)ch * G4 + n0) * 64;
        const char* sBl = (const char*)g_Wl + ((size_t)ch * G4 + n0) * 64;
#pragma unroll
        for (int i = 0; i < 2; i++) {
            uint32_t off = (uint32_t)(tid + i * 256) * 16;
            uint32_t so = sw64(off);
            cpa16s(tb + so,         sAh + off);
            cpa16s(tb + 8192 + so,  sAl + off);
            cpa16s(tb + 16384 + so, sBh + off);
            cpa16s(tb + 24576 + so, sBl + off);
        }
        cp_commit();
    };

    float C[4][4][4] = {};
    stage(0, 0);
    stage(1, 1);
    for (int it = 0; it < NCH; it++) {
        if (it < NCH - 1) { asm volatile("cp.async.wait_group 1;" ::: "memory"); }
        else              { asm volatile("cp.async.wait_group 0;" ::: "memory"); }
        __syncthreads();
        if (it + 2 < NCH) stage(it + 2, (it + 2) % 3);
        int buf = it % 3;
        uint32_t TA_h = sb + buf * 32768;
        uint32_t TA_l = TA_h + 8192;
        uint32_t TB_h = TA_h + 16384;
        uint32_t TB_l = TA_h + 24576;
#pragma unroll
        for (int ks = 0; ks < 2; ks++) {
            uint32_t bh[4][2], bl[4][2];
            uint32_t kbB = ks * 32 + ((lane >> 3) & 1) * 16;
#pragma unroll
            for (int nt = 0; nt < 4; nt++) {
                uint32_t offB = (uint32_t)(wn * 32 + nt * 8 + (lane & 7)) * 64 + kbB;
                ldsm_x2(bh[nt], TB_h + sw64(offB));
                ldsm_x2(bl[nt], TB_l + sw64(offB));
            }
            uint32_t kbA = ks * 32 + ((lane >> 4) & 1) * 16;
#pragma unroll
            for (int mt = 0; mt < 4; mt++) {
                uint32_t offA = (uint32_t)(wm * 64 + mt * 16 + (lane & 15)) * 64 + kbA;
                uint32_t ah[4], al[4];
                ldsm_x4(ah, TA_h + sw64(offA));
                ldsm_x4(al, TA_l + sw64(offA));
#pragma unroll
                for (int nt = 0; nt < 4; nt++) {
                    mma_bf16(C[mt][nt], ah, bh[nt]);
                    mma_bf16(C[mt][nt], ah, bl[nt]);
                    mma_bf16(C[mt][nt], al, bh[nt]);
                }
            }
        }
    }

#pragma unroll
    for (int mt = 0; mt < 4; mt++) {
#pragma unroll
        for (int nt = 0; nt < 4; nt++) {
            int cl = wn * 32 + nt * 8 + (lane & 3) * 2;
            int r0 = m0 + wm * 64 + mt * 16 + (lane >> 2);
            float b0 = sbias[cl], b1v = sbias[cl + 1];
            *(float2*)&g_preg[(size_t)r0 * G4 + n0 + cl] =
                make_float2(C[mt][nt][0] + b0, C[mt][nt][1] + b1v);
            *(float2*)&g_preg[(size_t)(r0 + 8) * G4 + n0 + cl] =
                make_float2(C[mt][nt][2] + b0, C[mt][nt][3] + b1v);
        }
    }
}

// ---------------- per-step scan: split-K (2 CTAs per col-group), atomic reduce into preg ----------------
__global__ __launch_bounds__(256) void k_step(int t) {
    extern __shared__ char sstep[];   // 3 x 24KB
    __shared__ int s_last;
    int tid = threadIdx.x, wid = tid >> 5, lane = tid & 31;
    int wm = wid & 1, wn = wid >> 1;
    int grp = blockIdx.x;          // 0..127 col-group
    int kh  = blockIdx.y;          // 0..1 K-half
    int u0 = grp * 16;
    int c0 = u0 * 4;
    int p_in = t & 1, p_out = (t + 1) & 1;
    uint32_t sb = smem_u32(sstep);
    int chbase = kh * 16;

    auto stage = [&](int ch, int buf) {
        uint32_t tb = sb + buf * 24576;
        const char* sA = (const char*)&g_hsp[p_in][ch][0][0][0];
#pragma unroll
        for (int i = 0; i < 2; i++) {
            uint32_t off = (uint32_t)(tid + i * 256) * 16;
            cpa16s(tb + (off & 4096) + sw128(off & 4095), sA + off);
        }
        const char* sBh = (const char*)g_U2h + ((size_t)ch * G4 + c0) * 128;
        const char* sBl = (const char*)g_U2l + ((size_t)ch * G4 + c0) * 128;
#pragma unroll
        for (int i = 0; i < 2; i++) {
            uint32_t off = (uint32_t)(tid + i * 256) * 16;
            uint32_t so = sw128(off);
            cpa16s(tb + 8192 + so,  sBh + off);
            cpa16s(tb + 16384 + so, sBl + off);
        }
        cp_commit();
    };

    float C[2][4] = {};
    stage(chbase, 0);
    stage(chbase + 1, 1);
    for (int it = 0; it < 16; it++) {
        if (it < 15) { asm volatile("cp.async.wait_group 1;" ::: "memory"); }
        else         { asm volatile("cp.async.wait_group 0;" ::: "memory"); }
        __syncthreads();
        if (it + 2 < 16) stage(chbase + it + 2, (it + 2) % 3);
        int buf = it % 3;
        uint32_t TA_h = sb + buf * 24576;
        uint32_t TA_l = TA_h + 4096;
        uint32_t TB_h = TA_h + 8192;
        uint32_t TB_l = TA_h + 16384;
#pragma unroll
        for (int ks = 0; ks < 4; ks++) {
            uint32_t bh[2][2], bl[2][2];
#pragma unroll
            for (int nt = 0; nt < 2; nt++) {
                uint32_t col = (uint32_t)(wn * 16 + nt * 8 + (lane & 7));
                uint32_t offB = col * 128 + ks * 32 + ((lane >> 3) & 1) * 16;
                ldsm_x2(bh[nt], TB_h + sw128(offB));
                ldsm_x2(bl[nt], TB_l + sw128(offB));
            }
            uint32_t kbA = ks * 32 + ((lane >> 4) & 1) * 16;
            uint32_t offA = (uint32_t)(wm * 16 + (lane & 15)) * 128 + kbA;
            uint32_t ah[4], al[4];
            ldsm_x4(ah, TA_h + sw128(offA));
            ldsm_x4(al, TA_l + sw128(offA));
#pragma unroll
            for (int nt = 0; nt < 2; nt++) {
                mma_bf16(C[nt], ah, bh[nt]);
                mma_bf16(C[nt], ah, bl[nt]);
                mma_bf16(C[nt], al, bh[nt]);
            }
        }
    }

    // reduce partials into preg (already holds bias + X@Wih^T)
    float* pregt = &g_preg[(size_t)t * BB * G4];
    {
        int b0 = wm * 16 + (lane >> 2);
#pragma unroll
        for (int nt = 0; nt < 2; nt++) {
            int cl = c0 + wn * 16 + nt * 8 + (lane & 3) * 2;
            atomicAdd(&pregt[(size_t)b0 * G4 + cl],           C[nt][0]);
            atomicAdd(&pregt[(size_t)b0 * G4 + cl + 1],       C[nt][1]);
            atomicAdd(&pregt[(size_t)(b0 + 8) * G4 + cl],     C[nt][2]);
            atomicAdd(&pregt[(size_t)(b0 + 8) * G4 + cl + 1], C[nt][3]);
        }
    }
    __threadfence();
    __syncthreads();
    if (tid == 0) s_last = (atomicAdd(&g_ctr[t * 128 + grp], 1) == 1);
    __syncthreads();
    if (!s_last) return;
    __threadfence();   // acquire: order gate reads after counter observation

    // last-arriving CTA: LSTM elementwise for this col-group (16 u x 32 b)
    float* __restrict__ hout = &g_hall[(size_t)t * HH * BB];
#pragma unroll
    for (int l = 0; l < 2; l++) {
        int p = tid + l * 256;
        int b = p & 31, uu = p >> 5;
        float4 pr = __ldcg((const float4*)&pregt[(size_t)b * G4 + (u0 + uu) * 4]);
        float gi = pr.x, gf = pr.y, gg = pr.z, go = pr.w;
        float si = 1.0f / (1.0f + expf(-gi));
        float sf_ = 1.0f / (1.0f + expf(-gf));
        float so = 1.0f / (1.0f + expf(-go));
        float tg = tanhf(gg);
        int u = u0 + uu;
        float c = sf_ * g_cT[u * BB + b] + si * tg;
        float hnew = so * tanhf(c);
        g_cT[u * BB + b] = c;
        hout[u * BB + b] = hnew;
        __nv_bfloat16 hh = __float2bfloat16(hnew);
        __nv_bfloat16 hl = __float2bfloat16(hnew - __bfloat162float(hh));
        g_hsp[p_out][u >> 6][0][b][u & 63] = hh;
        g_hsp[p_out][u >> 6][1][b][u & 63] = hl;
        size_t dm = ((size_t)(u >> 5) * TB + t * BB + b) * 32 + (u & 31);
        g_Xh[dm] = hh;
        g_Xl[dm] = hl;
    }
}

// ---------------- HMMA decoder: out = split3(H @ decW^T) + decb  [6400 x 256] ----------------
__global__ __launch_bounds__(256) void k_dmma(const float* __restrict__ decb,
                                              float* __restrict__ out) {
    extern __shared__ char dsm[];   // 3 x 32KB
    __shared__ float sbias[128];
    int tid = threadIdx.x, wid = tid >> 5, lane = tid & 31;
    int wm = wid & 1, wn = wid >> 1;
    int m0 = blockIdx.y * 128, n0 = blockIdx.x * 128;
    uint32_t sb = smem_u32(dsm);
    if (tid < 128) sbias[tid] = decb[n0 + tid];

    auto stage = [&](int ch, int buf) {
        uint32_t tb = sb + buf * 32768;
        const char* sAh = (const char*)g_Xh + ((size_t)ch * TB + m0) * 64;
        const char* sAl = (const char*)g_Xl + ((size_t)ch * TB + m0) * 64;
        const char* sBh = (const char*)g_Dh + ((size_t)ch * SS + n0) * 64;
        const char* sBl = (const char*)g_Dl + ((size_t)ch * SS + n0) * 64;
#pragma unroll
        for (int i = 0; i < 2; i++) {
            uint32_t off = (uint32_t)(tid + i * 256) * 16;
            uint32_t so = sw64(off);
            cpa16s(tb + so,         sAh + off);
            cpa16s(tb + 8192 + so,  sAl + off);
            cpa16s(tb + 16384 + so, sBh + off);
            cpa16s(tb + 24576 + so, sBl + off);
        }
        cp_commit();
    };

    float C[4][4][4] = {};
    stage(0, 0);
    stage(1, 1);
    for (int it = 0; it < NCH; it++) {
        if (it < NCH - 1) { asm volatile("cp.async.wait_group 1;" ::: "memory"); }
        else              { asm volatile("cp.async.wait_group 0;" ::: "memory"); }
        __syncthreads();
        if (it + 2 < NCH) stage(it + 2, (it + 2) % 3);
        int buf = it % 3;
        uint32_t TA_h = sb + buf * 32768;
        uint32_t TA_l = TA_h + 8192;
        uint32_t TB_h = TA_h + 16384;
        uint32_t TB_l = TA_h + 24576;
#pragma unroll
        for (int ks = 0; ks < 2; ks++) {
            uint32_t bh[4][2], bl[4][2];
            uint32_t kbB = ks * 32 + ((lane >> 3) & 1) * 16;
#pragma unroll
            for (int nt = 0; nt < 4; nt++) {
                uint32_t offB = (uint32_t)(wn * 32 + nt * 8 + (lane & 7)) * 64 + kbB;
                ldsm_x2(bh[nt], TB_h + sw64(offB));
                ldsm_x2(bl[nt], TB_l + sw64(offB));
            }
            uint32_t kbA = ks * 32 + ((lane >> 4) & 1) * 16;
#pragma unroll
            for (int mt = 0; mt < 4; mt++) {
                uint32_t offA = (uint32_t)(wm * 64 + mt * 16 + (lane & 15)) * 64 + kbA;
                uint32_t ah[4], al[4];
                ldsm_x4(ah, TA_h + sw64(offA));
                ldsm_x4(al, TA_l + sw64(offA));
#pragma unroll
                for (int nt = 0; nt < 4; nt++) {
                    mma_bf16(C[mt][nt], ah, bh[nt]);
                    mma_bf16(C[mt][nt], ah, bl[nt]);
                    mma_bf16(C[mt][nt], al, bh[nt]);
                }
            }
        }
    }

#pragma unroll
    for (int mt = 0; mt < 4; mt++) {
#pragma unroll
        for (int nt = 0; nt < 4; nt++) {
            int cl = wn * 32 + nt * 8 + (lane & 3) * 2;
            int r0 = m0 + wm * 64 + mt * 16 + (lane >> 2);
            float b0 = sbias[cl], b1v = sbias[cl + 1];
            int bb0 = r0 & 31, tt0 = r0 >> 5;
            *(float2*)&out[((size_t)bb0 * TT + tt0) * SS + n0 + cl] =
                make_float2(C[mt][nt][0] + b0, C[mt][nt][1] + b1v);
            int r1 = r0 + 8;
            int bb1 = r1 & 31, tt1 = r1 >> 5;
            *(float2*)&out[((size_t)bb1 * TT + tt1) * SS + n0 + cl] =
                make_float2(C[mt][nt][2] + b0, C[mt][nt][3] + b1v);
        }
    }
}

// ---------------- final state write-out ----------------
__global__ void k_finish(float* __restrict__ out, int out_size) {
    int i = blockIdx.x * blockDim.x + threadIdx.x;
    if (i < HH * BB) {
        int b = i / HH, k = i % HH;
        int base = TB * SS;
        const float* hlast = &g_hall[(size_t)(TT - 1) * HH * BB];
        if (base + i < out_size) out[base + i] = hlast[k * BB + b];
        if (base + HH * BB + i < out_size) out[base + HH * BB + i] = g_cT[k * BB + b];
    }
}

extern "C" void kernel_launch(void* const* d_in, const int* in_sizes, int n_in,
                              void* d_out, int out_size) {
    const float* in1  = (const float*)d_in[0];
    const float* in2  = (const float*)d_in[1];
    const float* h0   = (const float*)d_in[2];
    const float* c0   = (const float*)d_in[3];
    const int*   rt   = (const int*)  d_in[4];
    const float* m1W  = (const float*)d_in[5];
    const float* m1b  = (const float*)d_in[6];
    const float* m2W  = (const float*)d_in[7];
    const float* m2b  = (const float*)d_in[8];
    const float* encW = (const float*)d_in[9];
    const float* encb = (const float*)d_in[10];
    const float* Wih  = (const float*)d_in[11];
    const float* Whh  = (const float*)d_in[12];
    const float* bih  = (const float*)d_in[13];
    const float* bhh  = (const float*)d_in[14];
    const float* decW = (const float*)d_in[15];
    const float* decb = (const float*)d_in[16];
    float* out = (float*)d_out;

    const int HMMA_SMEM = 3 * 32768;   // 96KB
    const int STEP_SMEM = 3 * 24576;   // 72KB

    static int attr_done = 0;
    if (!attr_done) {
        cudaFuncSetAttribute(k_hmma, cudaFuncAttributeMaxDynamicSharedMemorySize, HMMA_SMEM);
        cudaFuncSetAttribute(k_dmma, cudaFuncAttributeMaxDynamicSharedMemorySize, HMMA_SMEM);
        cudaFuncSetAttribute(k_step, cudaFuncAttributeMaxDynamicSharedMemorySize, STEP_SMEM);
        attr_done = 1;
    }

    __nv_bfloat16 *wh, *wl;
    cudaGetSymbolAddress((void**)&wh, g_Wh);
    cudaGetSymbolAddress((void**)&wl, g_Wl);

    k_init<<<(HH * BB + 255) / 256, 256>>>(h0, c0);
    k_fused<<<(TB + 127) / 128, 128>>>(in1, in2, m1W, m1b, m2W, m2b);
    k_encode<<<TB, 256>>>(encW, encb, rt);
    k_splitX<<<dim3(TB / 256, NCH), 256>>>();
    k_splitW<<<dim3(G4 / 256, NCH), 256>>>(Wih, wh, wl, bih, bhh, 1);
    k_splitW64<<<dim3(G4 / 256, NC64), 256>>>(Whh);
    k_splitD<<<dim3(1, NCH), 256>>>(decW);
    k_hmma<<<dim3(G4 / 128, TB / 128), 256, HMMA_SMEM>>>();
    for (int t = 0; t < TT; t++)
        k_step<<<dim3(128, 2), 256, STEP_SMEM>>>(t);
    k_dmma<<<dim3(SS / 128, TB / 128), 256, HMMA_SMEM>>>(decb, out);
    k_finish<<<(HH * BB + 255) / 256, 256>>>(out, out_size);
}

// round 13
// speedup vs baseline: 1.3285x; 1.3285x over previous
#include <cuda_runtime.h>
#include <cuda_bf16.h>
#include <math.h>
#include <stdint.h>

#define BB 32
#define TT 200
#define HH 2048
#define G4 8192   // 4*H
#define SS 256
#define TB 6400   // T*B
#define FF 20
#define NCH 64    // K chunks of 32 (pregemm/dec)
#define NC64 32   // K chunks of 64 (scan)

typedef unsigned long long ull;

// ---- cp.async ----
__device__ __forceinline__ void cpa16s(uint32_t dst, const void* src) {
    asm volatile("cp.async.cg.shared.global [%0], [%1], 16;" :: "r"(dst), "l"(src));
}
__device__ __forceinline__ void cp_commit() { asm volatile("cp.async.commit_group;"); }

__device__ __forceinline__ uint32_t smem_u32(const void* p) {
    return (uint32_t)__cvta_generic_to_shared(p);
}
__device__ __forceinline__ uint32_t sw64(uint32_t off)  { return off ^ (((off >> 7) & 7u) << 4); }
__device__ __forceinline__ uint32_t sw128(uint32_t off) { return off ^ ((off >> 3) & 0x70u); }

// ---- ldmatrix / mma.sync (baseline PTX, legal on sm_103 non-'a') ----
__device__ __forceinline__ void ldsm_x4(uint32_t* r, uint32_t addr) {
    asm volatile("ldmatrix.sync.aligned.m8n8.x4.shared.b16 {%0,%1,%2,%3}, [%4];"
                 : "=r"(r[0]), "=r"(r[1]), "=r"(r[2]), "=r"(r[3]) : "r"(addr));
}
__device__ __forceinline__ void ldsm_x2(uint32_t* r, uint32_t addr) {
    asm volatile("ldmatrix.sync.aligned.m8n8.x2.shared.b16 {%0,%1}, [%2];"
                 : "=r"(r[0]), "=r"(r[1]) : "r"(addr));
}
__device__ __forceinline__ void mma_bf16(float* c, const uint32_t* a, const uint32_t* b) {
    asm volatile(
        "mma.sync.aligned.m16n8k16.row.col.f32.bf16.bf16.f32 "
        "{%0,%1,%2,%3}, {%4,%5,%6,%7}, {%8,%9}, {%0,%1,%2,%3};"
        : "+f"(c[0]), "+f"(c[1]), "+f"(c[2]), "+f"(c[3])
        : "r"(a[0]), "r"(a[1]), "r"(a[2]), "r"(a[3]), "r"(b[0]), "r"(b[1]));
}

// ---- scratch (device globals: allocation-free rule) ----
__device__ __align__(128) float g_fused[TB * FF];
__device__ __align__(128) float g_X[TB * HH];
// g_Xh/g_Xl: first hold split X for pregemm; after the scan they hold split h (dec A)
__device__ __align__(128) __nv_bfloat16 g_Xh[(size_t)NCH * TB * 32];
__device__ __align__(128) __nv_bfloat16 g_Xl[(size_t)NCH * TB * 32];
__device__ __align__(128) __nv_bfloat16 g_Wh[(size_t)NCH * G4 * 32];
__device__ __align__(128) __nv_bfloat16 g_Wl[(size_t)NCH * G4 * 32];
__device__ __align__(128) __nv_bfloat16 g_U2h[(size_t)NC64 * G4 * 64];
__device__ __align__(128) __nv_bfloat16 g_U2l[(size_t)NC64 * G4 * 64];
__device__ __align__(128) __nv_bfloat16 g_Dh[(size_t)NCH * SS * 32];   // decW hi
__device__ __align__(128) __nv_bfloat16 g_Dl[(size_t)NCH * SS * 32];   // decW lo
__device__ __align__(128) float g_bsum[G4];
__device__ __align__(128) float g_preg[(size_t)TB * G4];
__device__ __align__(128) float g_cT[HH * BB];
__device__ __align__(128) float g_hall[(size_t)TT * HH * BB];
__device__ __align__(128) __nv_bfloat16 g_hsp[2][NC64][2][32][64];

// ---------------- init: c transposed, h0 split ----------------
__global__ void k_init(const float* __restrict__ h0, const float* __restrict__ c0) {
    int i = blockIdx.x * blockDim.x + threadIdx.x;
    if (i < HH * BB) {
        int b = i >> 11, u = i & 2047;
        g_cT[u * BB + b] = c0[i];
        float x = h0[i];
        __nv_bfloat16 h = __float2bfloat16(x);
        __nv_bfloat16 l = __float2bfloat16(x - __bfloat162float(h));
        g_hsp[0][u >> 6][0][b][u & 63] = h;
        g_hsp[0][u >> 6][1][b][u & 63] = l;
    }
}

// ---------------- fused = [x1@m1^T+b1 , x2@m2^T+b2] ----------------
__global__ void k_fused(const float* __restrict__ in1, const float* __restrict__ in2,
                        const float* __restrict__ m1W, const float* __restrict__ m1b,
                        const float* __restrict__ m2W, const float* __restrict__ m2b) {
    int idx = blockIdx.x * blockDim.x + threadIdx.x;
    if (idx >= TB) return;
    int t = idx / BB, b = idx % BB;
    float x0 = in1[(b * TT + t) * 2 + 0];
    float x1 = in1[(b * TT + t) * 2 + 1];
    float x2 = in2[b * TT + t];
#pragma unroll
    for (int j = 0; j < 10; j++)
        g_fused[idx * FF + j] = m1W[j * 2] * x0 + m1W[j * 2 + 1] * x1 + m1b[j];
#pragma unroll
    for (int j = 0; j < 10; j++)
        g_fused[idx * FF + 10 + j] = m2W[j] * x2 + m2b[j];
}

// ---------------- expert encode ----------------
__global__ __launch_bounds__(256) void k_encode(const float* __restrict__ encW,
                                                const float* __restrict__ encb,
                                                const int* __restrict__ routers) {
    int idx = blockIdx.x;
    int t = idx / BB, b = idx % BB;
    int skill = routers[b * TT + t];
    __shared__ float sf[FF];
    if (threadIdx.x < FF) sf[threadIdx.x] = g_fused[idx * FF + threadIdx.x];
    __syncthreads();
    const float* Wbase = encW + (size_t)skill * FF * HH;
    const float* bbase = encb + skill * HH;
    for (int h = threadIdx.x; h < HH; h += 256) {
        float acc = bbase[h];
#pragma unroll
        for (int f = 0; f < FF; f++) acc += sf[f] * Wbase[f * HH + h];
        g_X[idx * HH + h] = acc;
    }
}

// ---------------- split X into chunk32-major bf16 hi/lo ----------------
__global__ __launch_bounds__(256) void k_splitX() {
    int m = blockIdx.x * 256 + threadIdx.x;
    int ch = blockIdx.y;
    const float* src = &g_X[(size_t)m * HH + ch * 32];
    union { __nv_bfloat16 b[32]; uint4 v[4]; } ph, pl;
#pragma unroll
    for (int i = 0; i < 32; i++) {
        float x = src[i];
        __nv_bfloat16 h = __float2bfloat16(x);
        ph.b[i] = h;
        pl.b[i] = __float2bfloat16(x - __bfloat162float(h));
    }
    size_t o = ((size_t)ch * TB + m) * 32;
#pragma unroll
    for (int i = 0; i < 4; i++) {
        *(uint4*)&g_Xh[o + i * 8] = ph.v[i];
        *(uint4*)&g_Xl[o + i * 8] = pl.v[i];
    }
}

// ---------------- split Wih into chunk32-major hi/lo + bias ----------------
__global__ __launch_bounds__(256) void k_splitW(const float* __restrict__ W,
                                                __nv_bfloat16* __restrict__ dh,
                                                __nv_bfloat16* __restrict__ dl,
                                                const float* __restrict__ b1,
                                                const float* __restrict__ b2,
                                                int do_bias) {
    int c = blockIdx.x * 256 + threadIdx.x;
    int ch = blockIdx.y;
    int j = (c & 3) * HH + (c >> 2);
    if (do_bias && ch == 0) g_bsum[c] = b1[j] + b2[j];
    const float* src = &W[(size_t)j * HH + ch * 32];
    union { __nv_bfloat16 b[32]; uint4 v[4]; } ph, pl;
#pragma unroll
    for (int i = 0; i < 32; i++) {
        float x = src[i];
        __nv_bfloat16 h = __float2bfloat16(x);
        ph.b[i] = h;
        pl.b[i] = __float2bfloat16(x - __bfloat162float(h));
    }
    size_t o = ((size_t)ch * G4 + c) * 32;
#pragma unroll
    for (int i = 0; i < 4; i++) {
        *(uint4*)&dh[o + i * 8] = ph.v[i];
        *(uint4*)&dl[o + i * 8] = pl.v[i];
    }
}

// ---------------- split decW (no interleave) into chunk32-major hi/lo ----------------
__global__ __launch_bounds__(256) void k_splitD(const float* __restrict__ W) {
    int s = threadIdx.x;
    int ch = blockIdx.y;
    const float* src = &W[(size_t)s * HH + ch * 32];
    union { __nv_bfloat16 b[32]; uint4 v[4]; } ph, pl;
#pragma unroll
    for (int i = 0; i < 32; i++) {
        float x = src[i];
        __nv_bfloat16 h = __float2bfloat16(x);
        ph.b[i] = h;
        pl.b[i] = __float2bfloat16(x - __bfloat162float(h));
    }
    size_t o = ((size_t)ch * SS + s) * 32;
#pragma unroll
    for (int i = 0; i < 4; i++) {
        *(uint4*)&g_Dh[o + i * 8] = ph.v[i];
        *(uint4*)&g_Dl[o + i * 8] = pl.v[i];
    }
}

// ---------------- split Whh into chunk64-major hi/lo ----------------
__global__ __launch_bounds__(256) void k_splitW64(const float* __restrict__ W) {
    int c = blockIdx.x * 256 + threadIdx.x;
    int ch = blockIdx.y;
    int j = (c & 3) * HH + (c >> 2);
    const float* src = &W[(size_t)j * HH + ch * 64];
    union { __nv_bfloat16 b[64]; uint4 v[8]; } ph, pl;
#pragma unroll
    for (int i = 0; i < 64; i++) {
        float x = src[i];
        __nv_bfloat16 h = __float2bfloat16(x);
        ph.b[i] = h;
        pl.b[i] = __float2bfloat16(x - __bfloat162float(h));
    }
    size_t o = ((size_t)ch * G4 + c) * 64;
#pragma unroll
    for (int i = 0; i < 8; i++) {
        *(uint4*)&g_U2h[o + i * 8] = ph.v[i];
        *(uint4*)&g_U2l[o + i * 8] = pl.v[i];
    }
}

// ---------------- HMMA pregemm: preg = split3(X @ Wih^T) + bias  [6400 x 8192] ----------------
__global__ __launch_bounds__(256) void k_hmma() {
    extern __shared__ char dsm[];   // 3 x 32KB
    __shared__ float sbias[128];
    int tid = threadIdx.x, wid = tid >> 5, lane = tid & 31;
    int wm = wid & 1, wn = wid >> 1;
    int m0 = blockIdx.y * 128, n0 = blockIdx.x * 128;
    uint32_t sb = smem_u32(dsm);
    if (tid < 128) sbias[tid] = g_bsum[n0 + tid];

    auto stage = [&](int ch, int buf) {
        uint32_t tb = sb + buf * 32768;
        const char* sAh = (const char*)g_Xh + ((size_t)ch * TB + m0) * 64;
        const char* sAl = (const char*)g_Xl + ((size_t)ch * TB + m0) * 64;
        const char* sBh = (const char*)g_Wh + ((size_t)ch * G4 + n0) * 64;
        const char* sBl = (const char*)g_Wl + ((size_t)ch * G4 + n0) * 64;
#pragma unroll
        for (int i = 0; i < 2; i++) {
            uint32_t off = (uint32_t)(tid + i * 256) * 16;
            uint32_t so = sw64(off);
            cpa16s(tb + so,         sAh + off);
            cpa16s(tb + 8192 + so,  sAl + off);
            cpa16s(tb + 16384 + so, sBh + off);
            cpa16s(tb + 24576 + so, sBl + off);
        }
        cp_commit();
    };

    float C[4][4][4] = {};
    stage(0, 0);
    stage(1, 1);
    for (int it = 0; it < NCH; it++) {
        if (it < NCH - 1) { asm volatile("cp.async.wait_group 1;" ::: "memory"); }
        else              { asm volatile("cp.async.wait_group 0;" ::: "memory"); }
        __syncthreads();
        if (it + 2 < NCH) stage(it + 2, (it + 2) % 3);
        int buf = it % 3;
        uint32_t TA_h = sb + buf * 32768;
        uint32_t TA_l = TA_h + 8192;
        uint32_t TB_h = TA_h + 16384;
        uint32_t TB_l = TA_h + 24576;
#pragma unroll
        for (int ks = 0; ks < 2; ks++) {
            uint32_t bh[4][2], bl[4][2];
            uint32_t kbB = ks * 32 + ((lane >> 3) & 1) * 16;
#pragma unroll
            for (int nt = 0; nt < 4; nt++) {
                uint32_t offB = (uint32_t)(wn * 32 + nt * 8 + (lane & 7)) * 64 + kbB;
                ldsm_x2(bh[nt], TB_h + sw64(offB));
                ldsm_x2(bl[nt], TB_l + sw64(offB));
            }
            uint32_t kbA = ks * 32 + ((lane >> 4) & 1) * 16;
#pragma unroll
            for (int mt = 0; mt < 4; mt++) {
                uint32_t offA = (uint32_t)(wm * 64 + mt * 16 + (lane & 15)) * 64 + kbA;
                uint32_t ah[4], al[4];
                ldsm_x4(ah, TA_h + sw64(offA));
                ldsm_x4(al, TA_l + sw64(offA));
#pragma unroll
                for (int nt = 0; nt < 4; nt++) {
                    mma_bf16(C[mt][nt], ah, bh[nt]);
                    mma_bf16(C[mt][nt], ah, bl[nt]);
                    mma_bf16(C[mt][nt], al, bh[nt]);
                }
            }
        }
    }

#pragma unroll
    for (int mt = 0; mt < 4; mt++) {
#pragma unroll
        for (int nt = 0; nt < 4; nt++) {
            int cl = wn * 32 + nt * 8 + (lane & 3) * 2;
            int r0 = m0 + wm * 64 + mt * 16 + (lane >> 2);
            float b0 = sbias[cl], b1v = sbias[cl + 1];
            *(float2*)&g_preg[(size_t)r0 * G4 + n0 + cl] =
                make_float2(C[mt][nt][0] + b0, C[mt][nt][1] + b1v);
            *(float2*)&g_preg[(size_t)(r0 + 8) * G4 + n0 + cl] =
                make_float2(C[mt][nt][2] + b0, C[mt][nt][3] + b1v);
        }
    }
}

// ---------------- per-step scan: 2 warp-groups split K in-CTA, smem reduce ----------------
__global__ __launch_bounds__(512) void k_step(int t) {
    extern __shared__ char sstep[];   // 2 wg x 3 x 24KB = 144KB
    __shared__ float gs[32][68];
    __shared__ float ps[32][68];
    int tid = threadIdx.x;
    int wg = tid >> 8;                // K-half
    int lt = tid & 255;
    int wid = lt >> 5, lane = lt & 31;
    int wm = wid & 1, wn = wid >> 1;
    int u0 = blockIdx.x * 16;
    int c0 = u0 * 4;
    int p_in = t & 1, p_out = (t + 1) & 1;
    uint32_t sb = smem_u32(sstep) + wg * 73728;
    int chbase = wg * 16;

    auto stage = [&](int ch, int buf) {
        uint32_t tb = sb + buf * 24576;
        const char* sA = (const char*)&g_hsp[p_in][ch][0][0][0];
#pragma unroll
        for (int i = 0; i < 2; i++) {
            uint32_t off = (uint32_t)(lt + i * 256) * 16;
            cpa16s(tb + (off & 4096) + sw128(off & 4095), sA + off);
        }
        const char* sBh = (const char*)g_U2h + ((size_t)ch * G4 + c0) * 128;
        const char* sBl = (const char*)g_U2l + ((size_t)ch * G4 + c0) * 128;
#pragma unroll
        for (int i = 0; i < 2; i++) {
            uint32_t off = (uint32_t)(lt + i * 256) * 16;
            uint32_t so = sw128(off);
            cpa16s(tb + 8192 + so,  sBh + off);
            cpa16s(tb + 16384 + so, sBl + off);
        }
        cp_commit();
    };

    float C[2][4] = {};
    stage(chbase, 0);
    stage(chbase + 1, 1);
    for (int it = 0; it < 16; it++) {
        if (it < 15) { asm volatile("cp.async.wait_group 1;" ::: "memory"); }
        else         { asm volatile("cp.async.wait_group 0;" ::: "memory"); }
        __syncthreads();
        if (it + 2 < 16) stage(chbase + it + 2, (it + 2) % 3);
        int buf = it % 3;
        uint32_t TA_h = sb + buf * 24576;
        uint32_t TA_l = TA_h + 4096;
        uint32_t TB_h = TA_h + 8192;
        uint32_t TB_l = TA_h + 16384;
#pragma unroll
        for (int ks = 0; ks < 4; ks++) {
            uint32_t bh[2][2], bl[2][2];
#pragma unroll
            for (int nt = 0; nt < 2; nt++) {
                uint32_t col = (uint32_t)(wn * 16 + nt * 8 + (lane & 7));
                uint32_t offB = col * 128 + ks * 32 + ((lane >> 3) & 1) * 16;
                ldsm_x2(bh[nt], TB_h + sw128(offB));
                ldsm_x2(bl[nt], TB_l + sw128(offB));
            }
            uint32_t kbA = ks * 32 + ((lane >> 4) & 1) * 16;
            uint32_t offA = (uint32_t)(wm * 16 + (lane & 15)) * 128 + kbA;
            uint32_t ah[4], al[4];
            ldsm_x4(ah, TA_h + sw128(offA));
            ldsm_x4(al, TA_l + sw128(offA));
#pragma unroll
            for (int nt = 0; nt < 2; nt++) {
                mma_bf16(C[nt], ah, bh[nt]);
                mma_bf16(C[nt], ah, bl[nt]);
                mma_bf16(C[nt], al, bh[nt]);
            }
        }
    }

    // wg1 publishes partials to smem
    if (wg == 1) {
#pragma unroll
        for (int nt = 0; nt < 2; nt++) {
            int b0 = wm * 16 + (lane >> 2);
            int cl = wn * 16 + nt * 8 + (lane & 3) * 2;
            ps[b0][cl] = C[nt][0];     ps[b0][cl + 1] = C[nt][1];
            ps[b0 + 8][cl] = C[nt][2]; ps[b0 + 8][cl + 1] = C[nt][3];
        }
    }
    __syncthreads();
    // wg0 reduces and stages final gate tile
    if (wg == 0) {
#pragma unroll
        for (int nt = 0; nt < 2; nt++) {
            int b0 = wm * 16 + (lane >> 2);
            int cl = wn * 16 + nt * 8 + (lane & 3) * 2;
            gs[b0][cl]         = C[nt][0] + ps[b0][cl];
            gs[b0][cl + 1]     = C[nt][1] + ps[b0][cl + 1];
            gs[b0 + 8][cl]     = C[nt][2] + ps[b0 + 8][cl];
            gs[b0 + 8][cl + 1] = C[nt][3] + ps[b0 + 8][cl + 1];
        }
    }
    __syncthreads();

    // LSTM elementwise: 512 (b,u) pairs, 1 per thread; also store bf16 h for dec
    float* __restrict__ hout = &g_hall[(size_t)t * HH * BB];
    {
        int p = tid;
        int b = p & 31, uu = p >> 5;   // uu 0..15
        float4 pr = *(const float4*)&g_preg[(size_t)(t * BB + b) * G4 + (u0 + uu) * 4];
        float gi = pr.x + gs[b][uu * 4 + 0];
        float gf = pr.y + gs[b][uu * 4 + 1];
        float gg = pr.z + gs[b][uu * 4 + 2];
        float go = pr.w + gs[b][uu * 4 + 3];
        float si = 1.0f / (1.0f + expf(-gi));
        float sf_ = 1.0f / (1.0f + expf(-gf));
        float so = 1.0f / (1.0f + expf(-go));
        float tg = tanhf(gg);
        int u = u0 + uu;
        float c = sf_ * g_cT[u * BB + b] + si * tg;
        float hnew = so * tanhf(c);
        g_cT[u * BB + b] = c;
        hout[u * BB + b] = hnew;
        __nv_bfloat16 hh = __float2bfloat16(hnew);
        __nv_bfloat16 hl = __float2bfloat16(hnew - __bfloat162float(hh));
        g_hsp[p_out][u >> 6][0][b][u & 63] = hh;
        g_hsp[p_out][u >> 6][1][b][u & 63] = hl;
        size_t dm = ((size_t)(u >> 5) * TB + t * BB + b) * 32 + (u & 31);
        g_Xh[dm] = hh;
        g_Xl[dm] = hl;
    }
}

// ---------------- HMMA decoder: out = split3(H @ decW^T) + decb  [6400 x 256] ----------------
__global__ __launch_bounds__(256) void k_dmma(const float* __restrict__ decb,
                                              float* __restrict__ out) {
    extern __shared__ char dsm[];   // 3 x 32KB
    __shared__ float sbias[128];
    int tid = threadIdx.x, wid = tid >> 5, lane = tid & 31;
    int wm = wid & 1, wn = wid >> 1;
    int m0 = blockIdx.y * 128, n0 = blockIdx.x * 128;
    uint32_t sb = smem_u32(dsm);
    if (tid < 128) sbias[tid] = decb[n0 + tid];

    auto stage = [&](int ch, int buf) {
        uint32_t tb = sb + buf * 32768;
        const char* sAh = (const char*)g_Xh + ((size_t)ch * TB + m0) * 64;
        const char* sAl = (const char*)g_Xl + ((size_t)ch * TB + m0) * 64;
        const char* sBh = (const char*)g_Dh + ((size_t)ch * SS + n0) * 64;
        const char* sBl = (const char*)g_Dl + ((size_t)ch * SS + n0) * 64;
#pragma unroll
        for (int i = 0; i < 2; i++) {
            uint32_t off = (uint32_t)(tid + i * 256) * 16;
            uint32_t so = sw64(off);
            cpa16s(tb + so,         sAh + off);
            cpa16s(tb + 8192 + so,  sAl + off);
            cpa16s(tb + 16384 + so, sBh + off);
            cpa16s(tb + 24576 + so, sBl + off);
        }
        cp_commit();
    };

    float C[4][4][4] = {};
    stage(0, 0);
    stage(1, 1);
    for (int it = 0; it < NCH; it++) {
        if (it < NCH - 1) { asm volatile("cp.async.wait_group 1;" ::: "memory"); }
        else              { asm volatile("cp.async.wait_group 0;" ::: "memory"); }
        __syncthreads();
        if (it + 2 < NCH) stage(it + 2, (it + 2) % 3);
        int buf = it % 3;
        uint32_t TA_h = sb + buf * 32768;
        uint32_t TA_l = TA_h + 8192;
        uint32_t TB_h = TA_h + 16384;
        uint32_t TB_l = TA_h + 24576;
#pragma unroll
        for (int ks = 0; ks < 2; ks++) {
            uint32_t bh[4][2], bl[4][2];
            uint32_t kbB = ks * 32 + ((lane >> 3) & 1) * 16;
#pragma unroll
            for (int nt = 0; nt < 4; nt++) {
                uint32_t offB = (uint32_t)(wn * 32 + nt * 8 + (lane & 7)) * 64 + kbB;
                ldsm_x2(bh[nt], TB_h + sw64(offB));
                ldsm_x2(bl[nt], TB_l + sw64(offB));
            }
            uint32_t kbA = ks * 32 + ((lane >> 4) & 1) * 16;
#pragma unroll
            for (int mt = 0; mt < 4; mt++) {
                uint32_t offA = (uint32_t)(wm * 64 + mt * 16 + (lane & 15)) * 64 + kbA;
                uint32_t ah[4], al[4];
                ldsm_x4(ah, TA_h + sw64(offA));
                ldsm_x4(al, TA_l + sw64(offA));
#pragma unroll
                for (int nt = 0; nt < 4; nt++) {
                    mma_bf16(C[mt][nt], ah, bh[nt]);
                    mma_bf16(C[mt][nt], ah, bl[nt]);
                    mma_bf16(C[mt][nt], al, bh[nt]);
                }
            }
        }
    }

#pragma unroll
    for (int mt = 0; mt < 4; mt++) {
#pragma unroll
        for (int nt = 0; nt < 4; nt++) {
            int cl = wn * 32 + nt * 8 + (lane & 3) * 2;
            int r0 = m0 + wm * 64 + mt * 16 + (lane >> 2);
            float b0 = sbias[cl], b1v = sbias[cl + 1];
            int bb0 = r0 & 31, tt0 = r0 >> 5;
            *(float2*)&out[((size_t)bb0 * TT + tt0) * SS + n0 + cl] =
                make_float2(C[mt][nt][0] + b0, C[mt][nt][1] + b1v);
            int r1 = r0 + 8;
            int bb1 = r1 & 31, tt1 = r1 >> 5;
            *(float2*)&out[((size_t)bb1 * TT + tt1) * SS + n0 + cl] =
                make_float2(C[mt][nt][2] + b0, C[mt][nt][3] + b1v);
        }
    }
}

// ---------------- final state write-out ----------------
__global__ void k_finish(float* __restrict__ out, int out_size) {
    int i = blockIdx.x * blockDim.x + threadIdx.x;
    if (i < HH * BB) {
        int b = i / HH, k = i % HH;
        int base = TB * SS;
        const float* hlast = &g_hall[(size_t)(TT - 1) * HH * BB];
        if (base + i < out_size) out[base + i] = hlast[k * BB + b];
        if (base + HH * BB + i < out_size) out[base + HH * BB + i] = g_cT[k * BB + b];
    }
}

extern "C" void kernel_launch(void* const* d_in, const int* in_sizes, int n_in,
                              void* d_out, int out_size) {
    const float* in1  = (const float*)d_in[0];
    const float* in2  = (const float*)d_in[1];
    const float* h0   = (const float*)d_in[2];
    const float* c0   = (const float*)d_in[3];
    const int*   rt   = (const int*)  d_in[4];
    const float* m1W  = (const float*)d_in[5];
    const float* m1b  = (const float*)d_in[6];
    const float* m2W  = (const float*)d_in[7];
    const float* m2b  = (const float*)d_in[8];
    const float* encW = (const float*)d_in[9];
    const float* encb = (const float*)d_in[10];
    const float* Wih  = (const float*)d_in[11];
    const float* Whh  = (const float*)d_in[12];
    const float* bih  = (const float*)d_in[13];
    const float* bhh  = (const float*)d_in[14];
    const float* decW = (const float*)d_in[15];
    const float* decb = (const float*)d_in[16];
    float* out = (float*)d_out;

    const int HMMA_SMEM = 3 * 32768;       // 96KB
    const int STEP_SMEM = 2 * 3 * 24576;   // 144KB (2 warp-group pipelines)

    static int attr_done = 0;
    if (!attr_done) {
        cudaFuncSetAttribute(k_hmma, cudaFuncAttributeMaxDynamicSharedMemorySize, HMMA_SMEM);
        cudaFuncSetAttribute(k_dmma, cudaFuncAttributeMaxDynamicSharedMemorySize, HMMA_SMEM);
        cudaFuncSetAttribute(k_step, cudaFuncAttributeMaxDynamicSharedMemorySize, STEP_SMEM);
        attr_done = 1;
    }

    __nv_bfloat16 *wh, *wl;
    cudaGetSymbolAddress((void**)&wh, g_Wh);
    cudaGetSymbolAddress((void**)&wl, g_Wl);

    k_init<<<(HH * BB + 255) / 256, 256>>>(h0, c0);
    k_fused<<<(TB + 127) / 128, 128>>>(in1, in2, m1W, m1b, m2W, m2b);
    k_encode<<<TB, 256>>>(encW, encb, rt);
    k_splitX<<<dim3(TB / 256, NCH), 256>>>();
    k_splitW<<<dim3(G4 / 256, NCH), 256>>>(Wih, wh, wl, bih, bhh, 1);
    k_splitW64<<<dim3(G4 / 256, NC64), 256>>>(Whh);
    k_splitD<<<dim3(1, NCH), 256>>>(decW);
    k_hmma<<<dim3(G4 / 128, TB / 128), 256, HMMA_SMEM>>>();
    for (int t = 0; t < TT; t++)
        k_step<<<128, 512, STEP_SMEM>>>(t);
    k_dmma<<<dim3(SS / 128, TB / 128), 256, HMMA_SMEM>>>(decb, out);
    k_finish<<<(HH * BB + 255) / 256, 256>>>(out, out_size);
}

// round 14
// speedup vs baseline: 1.3354x; 1.0052x over previous
#include <cuda_runtime.h>
#include <cuda_bf16.h>
#include <math.h>
#include <stdint.h>

#define BB 32
#define TT 200
#define HH 2048
#define G4 8192   // 4*H
#define SS 256
#define TB 6400   // T*B
#define FF 20
#define NCH 64    // K chunks of 32 (pregemm/dec)
#define NC64 32   // K chunks of 64 (scan)

typedef unsigned long long ull;

// ---- cp.async ----
__device__ __forceinline__ void cpa16s(uint32_t dst, const void* src) {
    asm volatile("cp.async.cg.shared.global [%0], [%1], 16;" :: "r"(dst), "l"(src));
}
__device__ __forceinline__ void cp_commit() { asm volatile("cp.async.commit_group;"); }

__device__ __forceinline__ uint32_t smem_u32(const void* p) {
    return (uint32_t)__cvta_generic_to_shared(p);
}
__device__ __forceinline__ uint32_t sw64(uint32_t off)  { return off ^ (((off >> 7) & 7u) << 4); }
__device__ __forceinline__ uint32_t sw128(uint32_t off) { return off ^ ((off >> 3) & 0x70u); }

// ---- ldmatrix / mma.sync (baseline PTX, legal on sm_103 non-'a') ----
__device__ __forceinline__ void ldsm_x4(uint32_t* r, uint32_t addr) {
    asm volatile("ldmatrix.sync.aligned.m8n8.x4.shared.b16 {%0,%1,%2,%3}, [%4];"
                 : "=r"(r[0]), "=r"(r[1]), "=r"(r[2]), "=r"(r[3]) : "r"(addr));
}
__device__ __forceinline__ void ldsm_x2(uint32_t* r, uint32_t addr) {
    asm volatile("ldmatrix.sync.aligned.m8n8.x2.shared.b16 {%0,%1}, [%2];"
                 : "=r"(r[0]), "=r"(r[1]) : "r"(addr));
}
__device__ __forceinline__ void mma_bf16(float* c, const uint32_t* a, const uint32_t* b) {
    asm volatile(
        "mma.sync.aligned.m16n8k16.row.col.f32.bf16.bf16.f32 "
        "{%0,%1,%2,%3}, {%4,%5,%6,%7}, {%8,%9}, {%0,%1,%2,%3};"
        : "+f"(c[0]), "+f"(c[1]), "+f"(c[2]), "+f"(c[3])
        : "r"(a[0]), "r"(a[1]), "r"(a[2]), "r"(a[3]), "r"(b[0]), "r"(b[1]));
}

// ---- scratch (device globals: allocation-free rule) ----
__device__ __align__(128) float g_fused[TB * FF];
__device__ __align__(128) float g_X[TB * HH];
// g_Xh/g_Xl: first hold split X for pregemm; after the scan they hold split h (dec A)
__device__ __align__(128) __nv_bfloat16 g_Xh[(size_t)NCH * TB * 32];
__device__ __align__(128) __nv_bfloat16 g_Xl[(size_t)NCH * TB * 32];
__device__ __align__(128) __nv_bfloat16 g_Wh[(size_t)NCH * G4 * 32];
__device__ __align__(128) __nv_bfloat16 g_Wl[(size_t)NCH * G4 * 32];
__device__ __align__(128) __nv_bfloat16 g_U2h[(size_t)NC64 * G4 * 64];
__device__ __align__(128) __nv_bfloat16 g_U2l[(size_t)NC64 * G4 * 64];
__device__ __align__(128) __nv_bfloat16 g_Dh[(size_t)NCH * SS * 32];   // decW hi
__device__ __align__(128) __nv_bfloat16 g_Dl[(size_t)NCH * SS * 32];   // decW lo
__device__ __align__(128) float g_bsum[G4];
__device__ __align__(128) float g_preg[(size_t)TB * G4];
__device__ __align__(128) float g_cT[HH * BB];
__device__ __align__(128) float g_hall[(size_t)TT * HH * BB];
__device__ __align__(128) __nv_bfloat16 g_hsp[2][NC64][2][32][64];
__device__ volatile int g_bar;   // persistent-scan grid barrier (zeroed each launch)

// ---------------- init: c transposed, h0 split, barrier reset ----------------
__global__ void k_init(const float* __restrict__ h0, const float* __restrict__ c0) {
    int i = blockIdx.x * blockDim.x + threadIdx.x;
    if (i == 0) g_bar = 0;
    if (i < HH * BB) {
        int b = i >> 11, u = i & 2047;
        g_cT[u * BB + b] = c0[i];
        float x = h0[i];
        __nv_bfloat16 h = __float2bfloat16(x);
        __nv_bfloat16 l = __float2bfloat16(x - __bfloat162float(h));
        g_hsp[0][u >> 6][0][b][u & 63] = h;
        g_hsp[0][u >> 6][1][b][u & 63] = l;
    }
}

// ---------------- fused = [x1@m1^T+b1 , x2@m2^T+b2] ----------------
__global__ void k_fused(const float* __restrict__ in1, const float* __restrict__ in2,
                        const float* __restrict__ m1W, const float* __restrict__ m1b,
                        const float* __restrict__ m2W, const float* __restrict__ m2b) {
    int idx = blockIdx.x * blockDim.x + threadIdx.x;
    if (idx >= TB) return;
    int t = idx / BB, b = idx % BB;
    float x0 = in1[(b * TT + t) * 2 + 0];
    float x1 = in1[(b * TT + t) * 2 + 1];
    float x2 = in2[b * TT + t];
#pragma unroll
    for (int j = 0; j < 10; j++)
        g_fused[idx * FF + j] = m1W[j * 2] * x0 + m1W[j * 2 + 1] * x1 + m1b[j];
#pragma unroll
    for (int j = 0; j < 10; j++)
        g_fused[idx * FF + 10 + j] = m2W[j] * x2 + m2b[j];
}

// ---------------- expert encode ----------------
__global__ __launch_bounds__(256) void k_encode(const float* __restrict__ encW,
                                                const float* __restrict__ encb,
                                                const int* __restrict__ routers) {
    int idx = blockIdx.x;
    int t = idx / BB, b = idx % BB;
    int skill = routers[b * TT + t];
    __shared__ float sf[FF];
    if (threadIdx.x < FF) sf[threadIdx.x] = g_fused[idx * FF + threadIdx.x];
    __syncthreads();
    const float* Wbase = encW + (size_t)skill * FF * HH;
    const float* bbase = encb + skill * HH;
    for (int h = threadIdx.x; h < HH; h += 256) {
        float acc = bbase[h];
#pragma unroll
        for (int f = 0; f < FF; f++) acc += sf[f] * Wbase[f * HH + h];
        g_X[idx * HH + h] = acc;
    }
}

// ---------------- split X into chunk32-major bf16 hi/lo ----------------
__global__ __launch_bounds__(256) void k_splitX() {
    int m = blockIdx.x * 256 + threadIdx.x;
    int ch = blockIdx.y;
    const float* src = &g_X[(size_t)m * HH + ch * 32];
    union { __nv_bfloat16 b[32]; uint4 v[4]; } ph, pl;
#pragma unroll
    for (int i = 0; i < 32; i++) {
        float x = src[i];
        __nv_bfloat16 h = __float2bfloat16(x);
        ph.b[i] = h;
        pl.b[i] = __float2bfloat16(x - __bfloat162float(h));
    }
    size_t o = ((size_t)ch * TB + m) * 32;
#pragma unroll
    for (int i = 0; i < 4; i++) {
        *(uint4*)&g_Xh[o + i * 8] = ph.v[i];
        *(uint4*)&g_Xl[o + i * 8] = pl.v[i];
    }
}

// ---------------- split Wih into chunk32-major hi/lo + bias ----------------
__global__ __launch_bounds__(256) void k_splitW(const float* __restrict__ W,
                                                __nv_bfloat16* __restrict__ dh,
                                                __nv_bfloat16* __restrict__ dl,
                                                const float* __restrict__ b1,
                                                const float* __restrict__ b2,
                                                int do_bias) {
    int c = blockIdx.x * 256 + threadIdx.x;
    int ch = blockIdx.y;
    int j = (c & 3) * HH + (c >> 2);
    if (do_bias && ch == 0) g_bsum[c] = b1[j] + b2[j];
    const float* src = &W[(size_t)j * HH + ch * 32];
    union { __nv_bfloat16 b[32]; uint4 v[4]; } ph, pl;
#pragma unroll
    for (int i = 0; i < 32; i++) {
        float x = src[i];
        __nv_bfloat16 h = __float2bfloat16(x);
        ph.b[i] = h;
        pl.b[i] = __float2bfloat16(x - __bfloat162float(h));
    }
    size_t o = ((size_t)ch * G4 + c) * 32;
#pragma unroll
    for (int i = 0; i < 4; i++) {
        *(uint4*)&dh[o + i * 8] = ph.v[i];
        *(uint4*)&dl[o + i * 8] = pl.v[i];
    }
}

// ---------------- split decW (no interleave) into chunk32-major hi/lo ----------------
__global__ __launch_bounds__(256) void k_splitD(const float* __restrict__ W) {
    int s = threadIdx.x;
    int ch = blockIdx.y;
    const float* src = &W[(size_t)s * HH + ch * 32];
    union { __nv_bfloat16 b[32]; uint4 v[4]; } ph, pl;
#pragma unroll
    for (int i = 0; i < 32; i++) {
        float x = src[i];
        __nv_bfloat16 h = __float2bfloat16(x);
        ph.b[i] = h;
        pl.b[i] = __float2bfloat16(x - __bfloat162float(h));
    }
    size_t o = ((size_t)ch * SS + s) * 32;
#pragma unroll
    for (int i = 0; i < 4; i++) {
        *(uint4*)&g_Dh[o + i * 8] = ph.v[i];
        *(uint4*)&g_Dl[o + i * 8] = pl.v[i];
    }
}

// ---------------- split Whh into chunk64-major hi/lo ----------------
__global__ __launch_bounds__(256) void k_splitW64(const float* __restrict__ W) {
    int c = blockIdx.x * 256 + threadIdx.x;
    int ch = blockIdx.y;
    int j = (c & 3) * HH + (c >> 2);
    const float* src = &W[(size_t)j * HH + ch * 64];
    union { __nv_bfloat16 b[64]; uint4 v[8]; } ph, pl;
#pragma unroll
    for (int i = 0; i < 64; i++) {
        float x = src[i];
        __nv_bfloat16 h = __float2bfloat16(x);
        ph.b[i] = h;
        pl.b[i] = __float2bfloat16(x - __bfloat162float(h));
    }
    size_t o = ((size_t)ch * G4 + c) * 64;
#pragma unroll
    for (int i = 0; i < 8; i++) {
        *(uint4*)&g_U2h[o + i * 8] = ph.v[i];
        *(uint4*)&g_U2l[o + i * 8] = pl.v[i];
    }
}

// ---------------- HMMA pregemm: preg = split3(X @ Wih^T) + bias  [6400 x 8192] ----------------
__global__ __launch_bounds__(256) void k_hmma() {
    extern __shared__ char dsm[];   // 3 x 32KB
    __shared__ float sbias[128];
    int tid = threadIdx.x, wid = tid >> 5, lane = tid & 31;
    int wm = wid & 1, wn = wid >> 1;
    int m0 = blockIdx.y * 128, n0 = blockIdx.x * 128;
    uint32_t sb = smem_u32(dsm);
    if (tid < 128) sbias[tid] = g_bsum[n0 + tid];

    auto stage = [&](int ch, int buf) {
        uint32_t tb = sb + buf * 32768;
        const char* sAh = (const char*)g_Xh + ((size_t)ch * TB + m0) * 64;
        const char* sAl = (const char*)g_Xl + ((size_t)ch * TB + m0) * 64;
        const char* sBh = (const char*)g_Wh + ((size_t)ch * G4 + n0) * 64;
        const char* sBl = (const char*)g_Wl + ((size_t)ch * G4 + n0) * 64;
#pragma unroll
        for (int i = 0; i < 2; i++) {
            uint32_t off = (uint32_t)(tid + i * 256) * 16;
            uint32_t so = sw64(off);
            cpa16s(tb + so,         sAh + off);
            cpa16s(tb + 8192 + so,  sAl + off);
            cpa16s(tb + 16384 + so, sBh + off);
            cpa16s(tb + 24576 + so, sBl + off);
        }
        cp_commit();
    };

    float C[4][4][4] = {};
    stage(0, 0);
    stage(1, 1);
    for (int it = 0; it < NCH; it++) {
        if (it < NCH - 1) { asm volatile("cp.async.wait_group 1;" ::: "memory"); }
        else              { asm volatile("cp.async.wait_group 0;" ::: "memory"); }
        __syncthreads();
        if (it + 2 < NCH) stage(it + 2, (it + 2) % 3);
        int buf = it % 3;
        uint32_t TA_h = sb + buf * 32768;
        uint32_t TA_l = TA_h + 8192;
        uint32_t TB_h = TA_h + 16384;
        uint32_t TB_l = TA_h + 24576;
#pragma unroll
        for (int ks = 0; ks < 2; ks++) {
            uint32_t bh[4][2], bl[4][2];
            uint32_t kbB = ks * 32 + ((lane >> 3) & 1) * 16;
#pragma unroll
            for (int nt = 0; nt < 4; nt++) {
                uint32_t offB = (uint32_t)(wn * 32 + nt * 8 + (lane & 7)) * 64 + kbB;
                ldsm_x2(bh[nt], TB_h + sw64(offB));
                ldsm_x2(bl[nt], TB_l + sw64(offB));
            }
            uint32_t kbA = ks * 32 + ((lane >> 4) & 1) * 16;
#pragma unroll
            for (int mt = 0; mt < 4; mt++) {
                uint32_t offA = (uint32_t)(wm * 64 + mt * 16 + (lane & 15)) * 64 + kbA;
                uint32_t ah[4], al[4];
                ldsm_x4(ah, TA_h + sw64(offA));
                ldsm_x4(al, TA_l + sw64(offA));
#pragma unroll
                for (int nt = 0; nt < 4; nt++) {
                    mma_bf16(C[mt][nt], ah, bh[nt]);
                    mma_bf16(C[mt][nt], ah, bl[nt]);
                    mma_bf16(C[mt][nt], al, bh[nt]);
                }
            }
        }
    }

#pragma unroll
    for (int mt = 0; mt < 4; mt++) {
#pragma unroll
        for (int nt = 0; nt < 4; nt++) {
            int cl = wn * 32 + nt * 8 + (lane & 3) * 2;
            int r0 = m0 + wm * 64 + mt * 16 + (lane >> 2);
            float b0 = sbias[cl], b1v = sbias[cl + 1];
            *(float2*)&g_preg[(size_t)r0 * G4 + n0 + cl] =
                make_float2(C[mt][nt][0] + b0, C[mt][nt][1] + b1v);
            *(float2*)&g_preg[(size_t)(r0 + 8) * G4 + n0 + cl] =
                make_float2(C[mt][nt][2] + b0, C[mt][nt][3] + b1v);
        }
    }
}

// ---------------- persistent scan: all 200 steps in one launch, grid barrier ----------------
__global__ __launch_bounds__(512) void k_scan() {
    extern __shared__ char sstep[];   // 2 wg x 3 x 24KB = 144KB
    __shared__ float gs[32][68];
    __shared__ float ps[32][68];
    int tid = threadIdx.x;
    int wg = tid >> 8;                // K-half
    int lt = tid & 255;
    int wid = lt >> 5, lane = lt & 31;
    int wm = wid & 1, wn = wid >> 1;
    int u0 = blockIdx.x * 16;
    int c0 = u0 * 4;
    uint32_t sb = smem_u32(sstep) + wg * 73728;
    int chbase = wg * 16;

    for (int t = 0; t < TT; t++) {
        int p_in = t & 1, p_out = (t + 1) & 1;

        auto stage = [&](int ch, int buf) {
            uint32_t tb = sb + buf * 24576;
            const char* sA = (const char*)&g_hsp[p_in][ch][0][0][0];
#pragma unroll
            for (int i = 0; i < 2; i++) {
                uint32_t off = (uint32_t)(lt + i * 256) * 16;
                cpa16s(tb + (off & 4096) + sw128(off & 4095), sA + off);
            }
            const char* sBh = (const char*)g_U2h + ((size_t)ch * G4 + c0) * 128;
            const char* sBl = (const char*)g_U2l + ((size_t)ch * G4 + c0) * 128;
#pragma unroll
            for (int i = 0; i < 2; i++) {
                uint32_t off = (uint32_t)(lt + i * 256) * 16;
                uint32_t so = sw128(off);
                cpa16s(tb + 8192 + so,  sBh + off);
                cpa16s(tb + 16384 + so, sBl + off);
            }
            cp_commit();
        };

        float C[2][4] = {};
        stage(chbase, 0);
        stage(chbase + 1, 1);
        for (int it = 0; it < 16; it++) {
            if (it < 15) { asm volatile("cp.async.wait_group 1;" ::: "memory"); }
            else         { asm volatile("cp.async.wait_group 0;" ::: "memory"); }
            __syncthreads();
            if (it + 2 < 16) stage(chbase + it + 2, (it + 2) % 3);
            int buf = it % 3;
            uint32_t TA_h = sb + buf * 24576;
            uint32_t TA_l = TA_h + 4096;
            uint32_t TB_h = TA_h + 8192;
            uint32_t TB_l = TA_h + 16384;
#pragma unroll
            for (int ks = 0; ks < 4; ks++) {
                uint32_t bh[2][2], bl[2][2];
#pragma unroll
                for (int nt = 0; nt < 2; nt++) {
                    uint32_t col = (uint32_t)(wn * 16 + nt * 8 + (lane & 7));
                    uint32_t offB = col * 128 + ks * 32 + ((lane >> 3) & 1) * 16;
                    ldsm_x2(bh[nt], TB_h + sw128(offB));
                    ldsm_x2(bl[nt], TB_l + sw128(offB));
                }
                uint32_t kbA = ks * 32 + ((lane >> 4) & 1) * 16;
                uint32_t offA = (uint32_t)(wm * 16 + (lane & 15)) * 128 + kbA;
                uint32_t ah[4], al[4];
                ldsm_x4(ah, TA_h + sw128(offA));
                ldsm_x4(al, TA_l + sw128(offA));
#pragma unroll
                for (int nt = 0; nt < 2; nt++) {
                    mma_bf16(C[nt], ah, bh[nt]);
                    mma_bf16(C[nt], ah, bl[nt]);
                    mma_bf16(C[nt], al, bh[nt]);
                }
            }
        }

        // wg1 publishes partials; wg0 reduces into gs
        if (wg == 1) {
#pragma unroll
            for (int nt = 0; nt < 2; nt++) {
                int b0 = wm * 16 + (lane >> 2);
                int cl = wn * 16 + nt * 8 + (lane & 3) * 2;
                ps[b0][cl] = C[nt][0];     ps[b0][cl + 1] = C[nt][1];
                ps[b0 + 8][cl] = C[nt][2]; ps[b0 + 8][cl + 1] = C[nt][3];
            }
        }
        __syncthreads();
        if (wg == 0) {
#pragma unroll
            for (int nt = 0; nt < 2; nt++) {
                int b0 = wm * 16 + (lane >> 2);
                int cl = wn * 16 + nt * 8 + (lane & 3) * 2;
                gs[b0][cl]         = C[nt][0] + ps[b0][cl];
                gs[b0][cl + 1]     = C[nt][1] + ps[b0][cl + 1];
                gs[b0 + 8][cl]     = C[nt][2] + ps[b0 + 8][cl];
                gs[b0 + 8][cl + 1] = C[nt][3] + ps[b0 + 8][cl + 1];
            }
        }
        __syncthreads();

        // LSTM elementwise: 512 (b,u) pairs, 1 per thread
        {
            float* __restrict__ hout = &g_hall[(size_t)t * HH * BB];
            int b = tid & 31, uu = tid >> 5;
            float4 pr = *(const float4*)&g_preg[(size_t)(t * BB + b) * G4 + (u0 + uu) * 4];
            float gi = pr.x + gs[b][uu * 4 + 0];
            float gf = pr.y + gs[b][uu * 4 + 1];
            float gg = pr.z + gs[b][uu * 4 + 2];
            float go = pr.w + gs[b][uu * 4 + 3];
            float si = 1.0f / (1.0f + expf(-gi));
            float sf_ = 1.0f / (1.0f + expf(-gf));
            float so = 1.0f / (1.0f + expf(-go));
            float tg = tanhf(gg);
            int u = u0 + uu;
            float c = sf_ * g_cT[u * BB + b] + si * tg;
            float hnew = so * tanhf(c);
            g_cT[u * BB + b] = c;
            hout[u * BB + b] = hnew;
            __nv_bfloat16 hh = __float2bfloat16(hnew);
            __nv_bfloat16 hl = __float2bfloat16(hnew - __bfloat162float(hh));
            g_hsp[p_out][u >> 6][0][b][u & 63] = hh;
            g_hsp[p_out][u >> 6][1][b][u & 63] = hl;
            size_t dm = ((size_t)(u >> 5) * TB + t * BB + b) * 32 + (u & 31);
            g_Xh[dm] = hh;
            g_Xl[dm] = hl;
        }

        // grid-wide barrier: make h visible, arrive, spin, acquire
        __threadfence();
        __syncthreads();
        if (tid == 0) {
            atomicAdd((int*)&g_bar, 1);
            int target = 128 * (t + 1);
            while (g_bar < target) __nanosleep(64);
        }
        __syncthreads();
        __threadfence();
    }
}

// ---------------- HMMA decoder: out = split3(H @ decW^T) + decb  [6400 x 256] ----------------
__global__ __launch_bounds__(256) void k_dmma(const float* __restrict__ decb,
                                              float* __restrict__ out) {
    extern __shared__ char dsm[];   // 3 x 32KB
    __shared__ float sbias[128];
    int tid = threadIdx.x, wid = tid >> 5, lane = tid & 31;
    int wm = wid & 1, wn = wid >> 1;
    int m0 = blockIdx.y * 128, n0 = blockIdx.x * 128;
    uint32_t sb = smem_u32(dsm);
    if (tid < 128) sbias[tid] = decb[n0 + tid];

    auto stage = [&](int ch, int buf) {
        uint32_t tb = sb + buf * 32768;
        const char* sAh = (const char*)g_Xh + ((size_t)ch * TB + m0) * 64;
        const char* sAl = (const char*)g_Xl + ((size_t)ch * TB + m0) * 64;
        const char* sBh = (const char*)g_Dh + ((size_t)ch * SS + n0) * 64;
        const char* sBl = (const char*)g_Dl + ((size_t)ch * SS + n0) * 64;
#pragma unroll
        for (int i = 0; i < 2; i++) {
            uint32_t off = (uint32_t)(tid + i * 256) * 16;
            uint32_t so = sw64(off);
            cpa16s(tb + so,         sAh + off);
            cpa16s(tb + 8192 + so,  sAl + off);
            cpa16s(tb + 16384 + so, sBh + off);
            cpa16s(tb + 24576 + so, sBl + off);
        }
        cp_commit();
    };

    float C[4][4][4] = {};
    stage(0, 0);
    stage(1, 1);
    for (int it = 0; it < NCH; it++) {
        if (it < NCH - 1) { asm volatile("cp.async.wait_group 1;" ::: "memory"); }
        else              { asm volatile("cp.async.wait_group 0;" ::: "memory"); }
        __syncthreads();
        if (it + 2 < NCH) stage(it + 2, (it + 2) % 3);
        int buf = it % 3;
        uint32_t TA_h = sb + buf * 32768;
        uint32_t TA_l = TA_h + 8192;
        uint32_t TB_h = TA_h + 16384;
        uint32_t TB_l = TA_h + 24576;
#pragma unroll
        for (int ks = 0; ks < 2; ks++) {
            uint32_t bh[4][2], bl[4][2];
            uint32_t kbB = ks * 32 + ((lane >> 3) & 1) * 16;
#pragma unroll
            for (int nt = 0; nt < 4; nt++) {
                uint32_t offB = (uint32_t)(wn * 32 + nt * 8 + (lane & 7)) * 64 + kbB;
                ldsm_x2(bh[nt], TB_h + sw64(offB));
                ldsm_x2(bl[nt], TB_l + sw64(offB));
            }
            uint32_t kbA = ks * 32 + ((lane >> 4) & 1) * 16;
#pragma unroll
            for (int mt = 0; mt < 4; mt++) {
                uint32_t offA = (uint32_t)(wm * 64 + mt * 16 + (lane & 15)) * 64 + kbA;
                uint32_t ah[4], al[4];
                ldsm_x4(ah, TA_h + sw64(offA));
                ldsm_x4(al, TA_l + sw64(offA));
#pragma unroll
                for (int nt = 0; nt < 4; nt++) {
                    mma_bf16(C[mt][nt], ah, bh[nt]);
                    mma_bf16(C[mt][nt], ah, bl[nt]);
                    mma_bf16(C[mt][nt], al, bh[nt]);
                }
            }
        }
    }

#pragma unroll
    for (int mt = 0; mt < 4; mt++) {
#pragma unroll
        for (int nt = 0; nt < 4; nt++) {
            int cl = wn * 32 + nt * 8 + (lane & 3) * 2;
            int r0 = m0 + wm * 64 + mt * 16 + (lane >> 2);
            float b0 = sbias[cl], b1v = sbias[cl + 1];
            int bb0 = r0 & 31, tt0 = r0 >> 5;
            *(float2*)&out[((size_t)bb0 * TT + tt0) * SS + n0 + cl] =
                make_float2(C[mt][nt][0] + b0, C[mt][nt][1] + b1v);
            int r1 = r0 + 8;
            int bb1 = r1 & 31, tt1 = r1 >> 5;
            *(float2*)&out[((size_t)bb1 * TT + tt1) * SS + n0 + cl] =
                make_float2(C[mt][nt][2] + b0, C[mt][nt][3] + b1v);
        }
    }
}

// ---------------- final state write-out ----------------
__global__ void k_finish(float* __restrict__ out, int out_size) {
    int i = blockIdx.x * blockDim.x + threadIdx.x;
    if (i < HH * BB) {
        int b = i / HH, k = i % HH;
        int base = TB * SS;
        const float* hlast = &g_hall[(size_t)(TT - 1) * HH * BB];
        if (base + i < out_size) out[base + i] = hlast[k * BB + b];
        if (base + HH * BB + i < out_size) out[base + HH * BB + i] = g_cT[k * BB + b];
    }
}

extern "C" void kernel_launch(void* const* d_in, const int* in_sizes, int n_in,
                              void* d_out, int out_size) {
    const float* in1  = (const float*)d_in[0];
    const float* in2  = (const float*)d_in[1];
    const float* h0   = (const float*)d_in[2];
    const float* c0   = (const float*)d_in[3];
    const int*   rt   = (const int*)  d_in[4];
    const float* m1W  = (const float*)d_in[5];
    const float* m1b  = (const float*)d_in[6];
    const float* m2W  = (const float*)d_in[7];
    const float* m2b  = (const float*)d_in[8];
    const float* encW = (const float*)d_in[9];
    const float* encb = (const float*)d_in[10];
    const float* Wih  = (const float*)d_in[11];
    const float* Whh  = (const float*)d_in[12];
    const float* bih  = (const float*)d_in[13];
    const float* bhh  = (const float*)d_in[14];
    const float* decW = (const float*)d_in[15];
    const float* decb = (const float*)d_in[16];
    float* out = (float*)d_out;

    const int HMMA_SMEM = 3 * 32768;       // 96KB
    const int STEP_SMEM = 2 * 3 * 24576;   // 144KB (2 warp-group pipelines)

    static int attr_done = 0;
    if (!attr_done) {
        cudaFuncSetAttribute(k_hmma, cudaFuncAttributeMaxDynamicSharedMemorySize, HMMA_SMEM);
        cudaFuncSetAttribute(k_dmma, cudaFuncAttributeMaxDynamicSharedMemorySize, HMMA_SMEM);
        cudaFuncSetAttribute(k_scan, cudaFuncAttributeMaxDynamicSharedMemorySize, STEP_SMEM);
        attr_done = 1;
    }

    __nv_bfloat16 *wh, *wl;
    cudaGetSymbolAddress((void**)&wh, g_Wh);
    cudaGetSymbolAddress((void**)&wl, g_Wl);

    k_init<<<(HH * BB + 255) / 256, 256>>>(h0, c0);
    k_fused<<<(TB + 127) / 128, 128>>>(in1, in2, m1W, m1b, m2W, m2b);
    k_encode<<<TB, 256>>>(encW, encb, rt);
    k_splitX<<<dim3(TB / 256, NCH), 256>>>();
    k_splitW<<<dim3(G4 / 256, NCH), 256>>>(Wih, wh, wl, bih, bhh, 1);
    k_splitW64<<<dim3(G4 / 256, NC64), 256>>>(Whh);
    k_splitD<<<dim3(1, NCH), 256>>>(decW);
    k_hmma<<<dim3(G4 / 128, TB / 128), 256, HMMA_SMEM>>>();
    k_scan<<<128, 512, STEP_SMEM>>>();
    k_dmma<<<dim3(SS / 128, TB / 128), 256, HMMA_SMEM>>>(decb, out);
    k_finish<<<(HH * BB + 255) / 256, 256>>>(out, out_size);
}

// round 15
// speedup vs baseline: 1.4720x; 1.1023x over previous
#include <cuda_runtime.h>
#include <cuda_bf16.h>
#include <math.h>
#include <stdint.h>

#define BB 32
#define TT 200
#define HH 2048
#define G4 8192   // 4*H
#define SS 256
#define TB 6400   // T*B
#define FF 20
#define NCH 64    // K chunks of 32 (pregemm/dec)
#define NC64 32   // K chunks of 64 (scan)

typedef unsigned long long ull;

// ---- cp.async ----
__device__ __forceinline__ void cpa16s(uint32_t dst, const void* src) {
    asm volatile("cp.async.cg.shared.global [%0], [%1], 16;" :: "r"(dst), "l"(src));
}
__device__ __forceinline__ void cp_commit() { asm volatile("cp.async.commit_group;"); }

__device__ __forceinline__ uint32_t smem_u32(const void* p) {
    return (uint32_t)__cvta_generic_to_shared(p);
}
__device__ __forceinline__ uint32_t sw64(uint32_t off)  { return off ^ (((off >> 7) & 7u) << 4); }
__device__ __forceinline__ uint32_t sw128(uint32_t off) { return off ^ ((off >> 3) & 0x70u); }

// ---- ldmatrix / mma.sync (baseline PTX, legal on sm_103 non-'a') ----
__device__ __forceinline__ void ldsm_x4(uint32_t* r, uint32_t addr) {
    asm volatile("ldmatrix.sync.aligned.m8n8.x4.shared.b16 {%0,%1,%2,%3}, [%4];"
                 : "=r"(r[0]), "=r"(r[1]), "=r"(r[2]), "=r"(r[3]) : "r"(addr));
}
__device__ __forceinline__ void ldsm_x2(uint32_t* r, uint32_t addr) {
    asm volatile("ldmatrix.sync.aligned.m8n8.x2.shared.b16 {%0,%1}, [%2];"
                 : "=r"(r[0]), "=r"(r[1]) : "r"(addr));
}
__device__ __forceinline__ void mma_bf16(float* c, const uint32_t* a, const uint32_t* b) {
    asm volatile(
        "mma.sync.aligned.m16n8k16.row.col.f32.bf16.bf16.f32 "
        "{%0,%1,%2,%3}, {%4,%5,%6,%7}, {%8,%9}, {%0,%1,%2,%3};"
        : "+f"(c[0]), "+f"(c[1]), "+f"(c[2]), "+f"(c[3])
        : "r"(a[0]), "r"(a[1]), "r"(a[2]), "r"(a[3]), "r"(b[0]), "r"(b[1]));
}
#define SLICE_BAR(id) asm volatile("bar.sync %0, 128;" :: "r"(id) : "memory")

// ---- scratch (device globals: allocation-free rule) ----
__device__ __align__(128) float g_fused[TB * FF];
__device__ __align__(128) float g_X[TB * HH];
// g_Xh/g_Xl: first hold split X for pregemm; after the scan they hold split h (dec A)
__device__ __align__(128) __nv_bfloat16 g_Xh[(size_t)NCH * TB * 32];
__device__ __align__(128) __nv_bfloat16 g_Xl[(size_t)NCH * TB * 32];
__device__ __align__(128) __nv_bfloat16 g_Wh[(size_t)NCH * G4 * 32];
__device__ __align__(128) __nv_bfloat16 g_Wl[(size_t)NCH * G4 * 32];
__device__ __align__(128) __nv_bfloat16 g_U2h[(size_t)NC64 * G4 * 64];
__device__ __align__(128) __nv_bfloat16 g_U2l[(size_t)NC64 * G4 * 64];
__device__ __align__(128) __nv_bfloat16 g_Dh[(size_t)NCH * SS * 32];   // decW hi
__device__ __align__(128) __nv_bfloat16 g_Dl[(size_t)NCH * SS * 32];   // decW lo
__device__ __align__(128) float g_bsum[G4];
__device__ __align__(128) float g_preg[(size_t)TB * G4];
__device__ __align__(128) float g_cT[HH * BB];
__device__ __align__(128) float g_hall[(size_t)TT * HH * BB];
__device__ __align__(128) __nv_bfloat16 g_hsp[2][NC64][2][32][64];
__device__ volatile int g_bar;   // persistent-scan grid barrier (zeroed each launch)

// ---------------- init: c transposed, h0 split, barrier reset ----------------
__global__ void k_init(const float* __restrict__ h0, const float* __restrict__ c0) {
    int i = blockIdx.x * blockDim.x + threadIdx.x;
    if (i == 0) g_bar = 0;
    if (i < HH * BB) {
        int b = i >> 11, u = i & 2047;
        g_cT[u * BB + b] = c0[i];
        float x = h0[i];
        __nv_bfloat16 h = __float2bfloat16(x);
        __nv_bfloat16 l = __float2bfloat16(x - __bfloat162float(h));
        g_hsp[0][u >> 6][0][b][u & 63] = h;
        g_hsp[0][u >> 6][1][b][u & 63] = l;
    }
}

// ---------------- fused = [x1@m1^T+b1 , x2@m2^T+b2] ----------------
__global__ void k_fused(const float* __restrict__ in1, const float* __restrict__ in2,
                        const float* __restrict__ m1W, const float* __restrict__ m1b,
                        const float* __restrict__ m2W, const float* __restrict__ m2b) {
    int idx = blockIdx.x * blockDim.x + threadIdx.x;
    if (idx >= TB) return;
    int t = idx / BB, b = idx % BB;
    float x0 = in1[(b * TT + t) * 2 + 0];
    float x1 = in1[(b * TT + t) * 2 + 1];
    float x2 = in2[b * TT + t];
#pragma unroll
    for (int j = 0; j < 10; j++)
        g_fused[idx * FF + j] = m1W[j * 2] * x0 + m1W[j * 2 + 1] * x1 + m1b[j];
#pragma unroll
    for (int j = 0; j < 10; j++)
        g_fused[idx * FF + 10 + j] = m2W[j] * x2 + m2b[j];
}

// ---------------- expert encode ----------------
__global__ __launch_bounds__(256) void k_encode(const float* __restrict__ encW,
                                                const float* __restrict__ encb,
                                                const int* __restrict__ routers) {
    int idx = blockIdx.x;
    int t = idx / BB, b = idx % BB;
    int skill = routers[b * TT + t];
    __shared__ float sf[FF];
    if (threadIdx.x < FF) sf[threadIdx.x] = g_fused[idx * FF + threadIdx.x];
    __syncthreads();
    const float* Wbase = encW + (size_t)skill * FF * HH;
    const float* bbase = encb + skill * HH;
    for (int h = threadIdx.x; h < HH; h += 256) {
        float acc = bbase[h];
#pragma unroll
        for (int f = 0; f < FF; f++) acc += sf[f] * Wbase[f * HH + h];
        g_X[idx * HH + h] = acc;
    }
}

// ---------------- split X into chunk32-major bf16 hi/lo ----------------
__global__ __launch_bounds__(256) void k_splitX() {
    int m = blockIdx.x * 256 + threadIdx.x;
    int ch = blockIdx.y;
    const float* src = &g_X[(size_t)m * HH + ch * 32];
    union { __nv_bfloat16 b[32]; uint4 v[4]; } ph, pl;
#pragma unroll
    for (int i = 0; i < 32; i++) {
        float x = src[i];
        __nv_bfloat16 h = __float2bfloat16(x);
        ph.b[i] = h;
        pl.b[i] = __float2bfloat16(x - __bfloat162float(h));
    }
    size_t o = ((size_t)ch * TB + m) * 32;
#pragma unroll
    for (int i = 0; i < 4; i++) {
        *(uint4*)&g_Xh[o + i * 8] = ph.v[i];
        *(uint4*)&g_Xl[o + i * 8] = pl.v[i];
    }
}

// ---------------- split Wih into chunk32-major hi/lo + bias ----------------
__global__ __launch_bounds__(256) void k_splitW(const float* __restrict__ W,
                                                __nv_bfloat16* __restrict__ dh,
                                                __nv_bfloat16* __restrict__ dl,
                                                const float* __restrict__ b1,
                                                const float* __restrict__ b2,
                                                int do_bias) {
    int c = blockIdx.x * 256 + threadIdx.x;
    int ch = blockIdx.y;
    int j = (c & 3) * HH + (c >> 2);
    if (do_bias && ch == 0) g_bsum[c] = b1[j] + b2[j];
    const float* src = &W[(size_t)j * HH + ch * 32];
    union { __nv_bfloat16 b[32]; uint4 v[4]; } ph, pl;
#pragma unroll
    for (int i = 0; i < 32; i++) {
        float x = src[i];
        __nv_bfloat16 h = __float2bfloat16(x);
        ph.b[i] = h;
        pl.b[i] = __float2bfloat16(x - __bfloat162float(h));
    }
    size_t o = ((size_t)ch * G4 + c) * 32;
#pragma unroll
    for (int i = 0; i < 4; i++) {
        *(uint4*)&dh[o + i * 8] = ph.v[i];
        *(uint4*)&dl[o + i * 8] = pl.v[i];
    }
}

// ---------------- split decW (no interleave) into chunk32-major hi/lo ----------------
__global__ __launch_bounds__(256) void k_splitD(const float* __restrict__ W) {
    int s = threadIdx.x;
    int ch = blockIdx.y;
    const float* src = &W[(size_t)s * HH + ch * 32];
    union { __nv_bfloat16 b[32]; uint4 v[4]; } ph, pl;
#pragma unroll
    for (int i = 0; i < 32; i++) {
        float x = src[i];
        __nv_bfloat16 h = __float2bfloat16(x);
        ph.b[i] = h;
        pl.b[i] = __float2bfloat16(x - __bfloat162float(h));
    }
    size_t o = ((size_t)ch * SS + s) * 32;
#pragma unroll
    for (int i = 0; i < 4; i++) {
        *(uint4*)&g_Dh[o + i * 8] = ph.v[i];
        *(uint4*)&g_Dl[o + i * 8] = pl.v[i];
    }
}

// ---------------- split Whh into chunk64-major hi/lo ----------------
__global__ __launch_bounds__(256) void k_splitW64(const float* __restrict__ W) {
    int c = blockIdx.x * 256 + threadIdx.x;
    int ch = blockIdx.y;
    int j = (c & 3) * HH + (c >> 2);
    const float* src = &W[(size_t)j * HH + ch * 64];
    union { __nv_bfloat16 b[64]; uint4 v[8]; } ph, pl;
#pragma unroll
    for (int i = 0; i < 64; i++) {
        float x = src[i];
        __nv_bfloat16 h = __float2bfloat16(x);
        ph.b[i] = h;
        pl.b[i] = __float2bfloat16(x - __bfloat162float(h));
    }
    size_t o = ((size_t)ch * G4 + c) * 64;
#pragma unroll
    for (int i = 0; i < 8; i++) {
        *(uint4*)&g_U2h[o + i * 8] = ph.v[i];
        *(uint4*)&g_U2l[o + i * 8] = pl.v[i];
    }
}

// ---------------- HMMA pregemm v2: 256x128 CTA tile ----------------
// 8 warps (4m x 2n), warp tile 64x64, chunk K=32, 2-stage cp.async.
__global__ __launch_bounds__(256, 1) void k_hmma() {
    extern __shared__ char dsm[];   // 2 x [Ah 16K | Al 16K | Bh 8K | Bl 8K] = 96KB
    __shared__ float sbias[128];
    int tid = threadIdx.x, wid = tid >> 5, lane = tid & 31;
    int wm = wid & 3, wn = wid >> 2;
    int m0 = blockIdx.y * 256, n0 = blockIdx.x * 128;
    uint32_t sb = smem_u32(dsm);
    if (tid < 128) sbias[tid] = g_bsum[n0 + tid];

    auto stage = [&](int ch, int buf) {
        uint32_t tb = sb + buf * 49152;
        const char* sAh = (const char*)g_Xh + ((size_t)ch * TB + m0) * 64;
        const char* sAl = (const char*)g_Xl + ((size_t)ch * TB + m0) * 64;
        const char* sBh = (const char*)g_Wh + ((size_t)ch * G4 + n0) * 64;
        const char* sBl = (const char*)g_Wl + ((size_t)ch * G4 + n0) * 64;
#pragma unroll
        for (int i = 0; i < 4; i++) {
            uint32_t off = (uint32_t)(tid + i * 256) * 16;   // 0..16383
            uint32_t so = sw64(off);
            cpa16s(tb + so,         sAh + off);
            cpa16s(tb + 16384 + so, sAl + off);
        }
#pragma unroll
        for (int i = 0; i < 2; i++) {
            uint32_t off = (uint32_t)(tid + i * 256) * 16;   // 0..8191
            uint32_t so = sw64(off);
            cpa16s(tb + 32768 + so, sBh + off);
            cpa16s(tb + 40960 + so, sBl + off);
        }
        cp_commit();
    };

    float C[4][8][4] = {};
    stage(0, 0);
    stage(1, 1);
    for (int it = 0; it < NCH; it++) {
        if (it < NCH - 1) { asm volatile("cp.async.wait_group 1;" ::: "memory"); }
        else              { asm volatile("cp.async.wait_group 0;" ::: "memory"); }
        __syncthreads();
        int buf = it & 1;
        uint32_t base = sb + buf * 49152;
#pragma unroll
        for (int ks = 0; ks < 2; ks++) {
            uint32_t bh[8][2], bl[8][2];
            uint32_t kbB = ks * 32 + ((lane >> 3) & 1) * 16;
#pragma unroll
            for (int nt = 0; nt < 8; nt++) {
                uint32_t offB = (uint32_t)(wn * 64 + nt * 8 + (lane & 7)) * 64 + kbB;
                ldsm_x2(bh[nt], base + 32768 + sw64(offB));
                ldsm_x2(bl[nt], base + 40960 + sw64(offB));
            }
            uint32_t kbA = ks * 32 + ((lane >> 4) & 1) * 16;
#pragma unroll
            for (int mt = 0; mt < 4; mt++) {
                uint32_t offA = (uint32_t)(wm * 64 + mt * 16 + (lane & 15)) * 64 + kbA;
                uint32_t ah[4], al[4];
                ldsm_x4(ah, base + sw64(offA));
                ldsm_x4(al, base + 16384 + sw64(offA));
#pragma unroll
                for (int nt = 0; nt < 8; nt++) {
                    mma_bf16(C[mt][nt], ah, bh[nt]);
                    mma_bf16(C[mt][nt], ah, bl[nt]);
                    mma_bf16(C[mt][nt], al, bh[nt]);
                }
            }
        }
        __syncthreads();
        if (it + 2 < NCH) stage(it + 2, buf);
    }
    asm volatile("cp.async.wait_group 0;" ::: "memory");

#pragma unroll
    for (int mt = 0; mt < 4; mt++) {
#pragma unroll
        for (int nt = 0; nt < 8; nt++) {
            int cl = wn * 64 + nt * 8 + (lane & 3) * 2;
            int r0 = m0 + wm * 64 + mt * 16 + (lane >> 2);
            float b0 = sbias[cl], b1v = sbias[cl + 1];
            *(float2*)&g_preg[(size_t)r0 * G4 + n0 + cl] =
                make_float2(C[mt][nt][0] + b0, C[mt][nt][1] + b1v);
            *(float2*)&g_preg[(size_t)(r0 + 8) * G4 + n0 + cl] =
                make_float2(C[mt][nt][2] + b0, C[mt][nt][3] + b1v);
        }
    }
}

// ---------------- persistent scan v2: 4 K-slices x 128 thr, named-barrier pipelines ----------------
__global__ __launch_bounds__(512) void k_scan() {
    extern __shared__ char sstep[];   // 4 slices x 2 stages x 24KB = 192KB
    __shared__ float gs[32][65];
    __shared__ float ps[3][32][65];
    int tid = threadIdx.x;
    int slice = tid >> 7;             // 0..3, K range [slice*512, +512)
    int lt = tid & 127;
    int wid = lt >> 5, lane = lt & 31;
    int wm = wid & 1, wn = wid >> 1;  // wm: m16 half, wn: 32-col half
    int u0 = blockIdx.x * 16;
    int c0 = u0 * 4;
    uint32_t sb = smem_u32(sstep) + slice * 49152;
    int chbase = slice * 8;
    int barid = slice + 1;

    for (int t = 0; t < TT; t++) {
        int p_in = t & 1, p_out = (t + 1) & 1;

        auto stage = [&](int ch, int buf) {
            uint32_t tb = sb + buf * 24576;
            const char* sA = (const char*)&g_hsp[p_in][ch][0][0][0];
#pragma unroll
            for (int i = 0; i < 4; i++) {
                uint32_t off = (uint32_t)(lt + i * 128) * 16;   // 0..8191
                cpa16s(tb + (off & 4096) + sw128(off & 4095), sA + off);
            }
            const char* sBh = (const char*)g_U2h + ((size_t)ch * G4 + c0) * 128;
            const char* sBl = (const char*)g_U2l + ((size_t)ch * G4 + c0) * 128;
#pragma unroll
            for (int i = 0; i < 4; i++) {
                uint32_t off = (uint32_t)(lt + i * 128) * 16;   // 0..8191
                uint32_t so = sw128(off);
                cpa16s(tb + 8192 + so,  sBh + off);
                cpa16s(tb + 16384 + so, sBl + off);
            }
            cp_commit();
        };

        float C[4][4] = {};
        stage(chbase, 0);
        stage(chbase + 1, 1);
        for (int it = 0; it < 8; it++) {
            if (it < 7) { asm volatile("cp.async.wait_group 1;" ::: "memory"); }
            else        { asm volatile("cp.async.wait_group 0;" ::: "memory"); }
            SLICE_BAR(barid);
            int buf = it & 1;
            uint32_t tb = sb + buf * 24576;
            uint32_t TA_h = tb, TA_l = tb + 4096;
            uint32_t TB_h = tb + 8192, TB_l = tb + 16384;
#pragma unroll
            for (int ks = 0; ks < 4; ks++) {
                uint32_t bh[4][2], bl[4][2];
#pragma unroll
                for (int nt = 0; nt < 4; nt++) {
                    uint32_t offB = (uint32_t)(wn * 32 + nt * 8 + (lane & 7)) * 128
                                  + ks * 32 + ((lane >> 3) & 1) * 16;
                    ldsm_x2(bh[nt], TB_h + sw128(offB));
                    ldsm_x2(bl[nt], TB_l + sw128(offB));
                }
                uint32_t offA = (uint32_t)(wm * 16 + (lane & 15)) * 128
                              + ks * 32 + ((lane >> 4) & 1) * 16;
                uint32_t ah[4], al[4];
                ldsm_x4(ah, TA_h + sw128(offA));
                ldsm_x4(al, TA_l + sw128(offA));
#pragma unroll
                for (int nt = 0; nt < 4; nt++) {
                    mma_bf16(C[nt], ah, bh[nt]);
                    mma_bf16(C[nt], ah, bl[nt]);
                    mma_bf16(C[nt], al, bh[nt]);
                }
            }
            SLICE_BAR(barid);
            if (it + 2 < 8) stage(chbase + it + 2, buf);
        }

        // cross-slice reduction via smem
        __syncthreads();
        if (slice != 0) {
            float (*pp)[65] = ps[slice - 1];
#pragma unroll
            for (int nt = 0; nt < 4; nt++) {
                int b0 = wm * 16 + (lane >> 2);
                int cl = wn * 32 + nt * 8 + (lane & 3) * 2;
                pp[b0][cl] = C[nt][0];     pp[b0][cl + 1] = C[nt][1];
                pp[b0 + 8][cl] = C[nt][2]; pp[b0 + 8][cl + 1] = C[nt][3];
            }
        }
        __syncthreads();
        if (slice == 0) {
#pragma unroll
            for (int nt = 0; nt < 4; nt++) {
                int b0 = wm * 16 + (lane >> 2);
                int cl = wn * 32 + nt * 8 + (lane & 3) * 2;
                gs[b0][cl]         = C[nt][0] + ps[0][b0][cl] + ps[1][b0][cl] + ps[2][b0][cl];
                gs[b0][cl + 1]     = C[nt][1] + ps[0][b0][cl + 1] + ps[1][b0][cl + 1] + ps[2][b0][cl + 1];
                gs[b0 + 8][cl]     = C[nt][2] + ps[0][b0 + 8][cl] + ps[1][b0 + 8][cl] + ps[2][b0 + 8][cl];
                gs[b0 + 8][cl + 1] = C[nt][3] + ps[0][b0 + 8][cl + 1] + ps[1][b0 + 8][cl + 1] + ps[2][b0 + 8][cl + 1];
            }
        }
        __syncthreads();

        // LSTM elementwise: 512 (b,u) pairs, 1 per thread
        {
            float* __restrict__ hout = &g_hall[(size_t)t * HH * BB];
            int b = tid & 31, uu = tid >> 5;
            float4 pr = *(const float4*)&g_preg[(size_t)(t * BB + b) * G4 + (u0 + uu) * 4];
            float gi = pr.x + gs[b][uu * 4 + 0];
            float gf = pr.y + gs[b][uu * 4 + 1];
            float gg = pr.z + gs[b][uu * 4 + 2];
            float go = pr.w + gs[b][uu * 4 + 3];
            float si = 1.0f / (1.0f + expf(-gi));
            float sf_ = 1.0f / (1.0f + expf(-gf));
            float so = 1.0f / (1.0f + expf(-go));
            float tg = tanhf(gg);
            int u = u0 + uu;
            float c = sf_ * g_cT[u * BB + b] + si * tg;
            float hnew = so * tanhf(c);
            g_cT[u * BB + b] = c;
            hout[u * BB + b] = hnew;
            __nv_bfloat16 hh = __float2bfloat16(hnew);
            __nv_bfloat16 hl = __float2bfloat16(hnew - __bfloat162float(hh));
            g_hsp[p_out][u >> 6][0][b][u & 63] = hh;
            g_hsp[p_out][u >> 6][1][b][u & 63] = hl;
            size_t dm = ((size_t)(u >> 5) * TB + t * BB + b) * 32 + (u & 31);
            g_Xh[dm] = hh;
            g_Xl[dm] = hl;
        }

        // grid-wide barrier
        __threadfence();
        __syncthreads();
        if (tid == 0) {
            atomicAdd((int*)&g_bar, 1);
            int target = 128 * (t + 1);
            while (g_bar < target) __nanosleep(64);
        }
        __syncthreads();
        __threadfence();
    }
}

// ---------------- HMMA decoder: out = split3(H @ decW^T) + decb  [6400 x 256] ----------------
__global__ __launch_bounds__(256) void k_dmma(const float* __restrict__ decb,
                                              float* __restrict__ out) {
    extern __shared__ char dsm[];   // 3 x 32KB
    __shared__ float sbias[128];
    int tid = threadIdx.x, wid = tid >> 5, lane = tid & 31;
    int wm = wid & 1, wn = wid >> 1;
    int m0 = blockIdx.y * 128, n0 = blockIdx.x * 128;
    uint32_t sb = smem_u32(dsm);
    if (tid < 128) sbias[tid] = decb[n0 + tid];

    auto stage = [&](int ch, int buf) {
        uint32_t tb = sb + buf * 32768;
        const char* sAh = (const char*)g_Xh + ((size_t)ch * TB + m0) * 64;
        const char* sAl = (const char*)g_Xl + ((size_t)ch * TB + m0) * 64;
        const char* sBh = (const char*)g_Dh + ((size_t)ch * SS + n0) * 64;
        const char* sBl = (const char*)g_Dl + ((size_t)ch * SS + n0) * 64;
#pragma unroll
        for (int i = 0; i < 2; i++) {
            uint32_t off = (uint32_t)(tid + i * 256) * 16;
            uint32_t so = sw64(off);
            cpa16s(tb + so,         sAh + off);
            cpa16s(tb + 8192 + so,  sAl + off);
            cpa16s(tb + 16384 + so, sBh + off);
            cpa16s(tb + 24576 + so, sBl + off);
        }
        cp_commit();
    };

    float C[4][4][4] = {};
    stage(0, 0);
    stage(1, 1);
    for (int it = 0; it < NCH; it++) {
        if (it < NCH - 1) { asm volatile("cp.async.wait_group 1;" ::: "memory"); }
        else              { asm volatile("cp.async.wait_group 0;" ::: "memory"); }
        __syncthreads();
        if (it + 2 < NCH) stage(it + 2, (it + 2) % 3);
        int buf = it % 3;
        uint32_t TA_h = sb + buf * 32768;
        uint32_t TA_l = TA_h + 8192;
        uint32_t TB_h = TA_h + 16384;
        uint32_t TB_l = TA_h + 24576;
#pragma unroll
        for (int ks = 0; ks < 2; ks++) {
            uint32_t bh[4][2], bl[4][2];
            uint32_t kbB = ks * 32 + ((lane >> 3) & 1) * 16;
#pragma unroll
            for (int nt = 0; nt < 4; nt++) {
                uint32_t offB = (uint32_t)(wn * 32 + nt * 8 + (lane & 7)) * 64 + kbB;
                ldsm_x2(bh[nt], TB_h + sw64(offB));
                ldsm_x2(bl[nt], TB_l + sw64(offB));
            }
            uint32_t kbA = ks * 32 + ((lane >> 4) & 1) * 16;
#pragma unroll
            for (int mt = 0; mt < 4; mt++) {
                uint32_t offA = (uint32_t)(wm * 64 + mt * 16 + (lane & 15)) * 64 + kbA;
                uint32_t ah[4], al[4];
                ldsm_x4(ah, TA_h + sw64(offA));
                ldsm_x4(al, TA_l + sw64(offA));
#pragma unroll
                for (int nt = 0; nt < 4; nt++) {
                    mma_bf16(C[mt][nt], ah, bh[nt]);
                    mma_bf16(C[mt][nt], ah, bl[nt]);
                    mma_bf16(C[mt][nt], al, bh[nt]);
                }
            }
        }
    }

#pragma unroll
    for (int mt = 0; mt < 4; mt++) {
#pragma unroll
        for (int nt = 0; nt < 4; nt++) {
            int cl = wn * 32 + nt * 8 + (lane & 3) * 2;
            int r0 = m0 + wm * 64 + mt * 16 + (lane >> 2);
            float b0 = sbias[cl], b1v = sbias[cl + 1];
            int bb0 = r0 & 31, tt0 = r0 >> 5;
            *(float2*)&out[((size_t)bb0 * TT + tt0) * SS + n0 + cl] =
                make_float2(C[mt][nt][0] + b0, C[mt][nt][1] + b1v);
            int r1 = r0 + 8;
            int bb1 = r1 & 31, tt1 = r1 >> 5;
            *(float2*)&out[((size_t)bb1 * TT + tt1) * SS + n0 + cl] =
                make_float2(C[mt][nt][2] + b0, C[mt][nt][3] + b1v);
        }
    }
}

// ---------------- final state write-out ----------------
__global__ void k_finish(float* __restrict__ out, int out_size) {
    int i = blockIdx.x * blockDim.x + threadIdx.x;
    if (i < HH * BB) {
        int b = i / HH, k = i % HH;
        int base = TB * SS;
        const float* hlast = &g_hall[(size_t)(TT - 1) * HH * BB];
        if (base + i < out_size) out[base + i] = hlast[k * BB + b];
        if (base + HH * BB + i < out_size) out[base + HH * BB + i] = g_cT[k * BB + b];
    }
}

extern "C" void kernel_launch(void* const* d_in, const int* in_sizes, int n_in,
                              void* d_out, int out_size) {
    const float* in1  = (const float*)d_in[0];
    const float* in2  = (const float*)d_in[1];
    const float* h0   = (const float*)d_in[2];
    const float* c0   = (const float*)d_in[3];
    const int*   rt   = (const int*)  d_in[4];
    const float* m1W  = (const float*)d_in[5];
    const float* m1b  = (const float*)d_in[6];
    const float* m2W  = (const float*)d_in[7];
    const float* m2b  = (const float*)d_in[8];
    const float* encW = (const float*)d_in[9];
    const float* encb = (const float*)d_in[10];
    const float* Wih  = (const float*)d_in[11];
    const float* Whh  = (const float*)d_in[12];
    const float* bih  = (const float*)d_in[13];
    const float* bhh  = (const float*)d_in[14];
    const float* decW = (const float*)d_in[15];
    const float* decb = (const float*)d_in[16];
    float* out = (float*)d_out;

    const int HMMA_SMEM = 2 * 49152;       // 96KB
    const int SCAN_SMEM = 4 * 2 * 24576;   // 192KB
    const int DMMA_SMEM = 3 * 32768;       // 96KB

    static int attr_done = 0;
    if (!attr_done) {
        cudaFuncSetAttribute(k_hmma, cudaFuncAttributeMaxDynamicSharedMemorySize, HMMA_SMEM);
        cudaFuncSetAttribute(k_dmma, cudaFuncAttributeMaxDynamicSharedMemorySize, DMMA_SMEM);
        cudaFuncSetAttribute(k_scan, cudaFuncAttributeMaxDynamicSharedMemorySize, SCAN_SMEM);
        attr_done = 1;
    }

    __nv_bfloat16 *wh, *wl;
    cudaGetSymbolAddress((void**)&wh, g_Wh);
    cudaGetSymbolAddress((void**)&wl, g_Wl);

    k_init<<<(HH * BB + 255) / 256, 256>>>(h0, c0);
    k_fused<<<(TB + 127) / 128, 128>>>(in1, in2, m1W, m1b, m2W, m2b);
    k_encode<<<TB, 256>>>(encW, encb, rt);
    k_splitX<<<dim3(TB / 256, NCH), 256>>>();
    k_splitW<<<dim3(G4 / 256, NCH), 256>>>(Wih, wh, wl, bih, bhh, 1);
    k_splitW64<<<dim3(G4 / 256, NC64), 256>>>(Whh);
    k_splitD<<<dim3(1, NCH), 256>>>(decW);
    k_hmma<<<dim3(G4 / 128, TB / 256), 256, HMMA_SMEM>>>();
    k_scan<<<128, 512, SCAN_SMEM>>>();
    k_dmma<<<dim3(SS / 128, TB / 128), 256, DMMA_SMEM>>>(decb, out);
    k_finish<<<(HH * BB + 255) / 256, 256>>>(out, out_size);
}

// round 16
// speedup vs baseline: 1.5573x; 1.0580x over previous
#include <cuda_runtime.h>
#include <cuda_bf16.h>
#include <math.h>
#include <stdint.h>

#define BB 32
#define TT 200
#define HH 2048
#define G4 8192   // 4*H
#define SS 256
#define TB 6400   // T*B
#define FF 20
#define NCH 64    // K chunks of 32 (pregemm/dec)
#define NC64 32   // K chunks of 64 (scan)

typedef unsigned long long ull;

// ---- cp.async ----
__device__ __forceinline__ void cpa16s(uint32_t dst, const void* src) {
    asm volatile("cp.async.cg.shared.global [%0], [%1], 16;" :: "r"(dst), "l"(src));
}
__device__ __forceinline__ void cp_commit() { asm volatile("cp.async.commit_group;"); }

__device__ __forceinline__ uint32_t smem_u32(const void* p) {
    return (uint32_t)__cvta_generic_to_shared(p);
}
__device__ __forceinline__ uint32_t sw64(uint32_t off)  { return off ^ (((off >> 7) & 7u) << 4); }
__device__ __forceinline__ uint32_t sw128(uint32_t off) { return off ^ ((off >> 3) & 0x70u); }

// ---- ldmatrix / mma.sync (baseline PTX, legal on sm_103 non-'a') ----
__device__ __forceinline__ void ldsm_x4(uint32_t* r, uint32_t addr) {
    asm volatile("ldmatrix.sync.aligned.m8n8.x4.shared.b16 {%0,%1,%2,%3}, [%4];"
                 : "=r"(r[0]), "=r"(r[1]), "=r"(r[2]), "=r"(r[3]) : "r"(addr));
}
__device__ __forceinline__ void ldsm_x2(uint32_t* r, uint32_t addr) {
    asm volatile("ldmatrix.sync.aligned.m8n8.x2.shared.b16 {%0,%1}, [%2];"
                 : "=r"(r[0]), "=r"(r[1]) : "r"(addr));
}
__device__ __forceinline__ void mma_bf16(float* c, const uint32_t* a, const uint32_t* b) {
    asm volatile(
        "mma.sync.aligned.m16n8k16.row.col.f32.bf16.bf16.f32 "
        "{%0,%1,%2,%3}, {%4,%5,%6,%7}, {%8,%9}, {%0,%1,%2,%3};"
        : "+f"(c[0]), "+f"(c[1]), "+f"(c[2]), "+f"(c[3])
        : "r"(a[0]), "r"(a[1]), "r"(a[2]), "r"(a[3]), "r"(b[0]), "r"(b[1]));
}
#define SLICE_BAR(id) asm volatile("bar.sync %0, 128;" :: "r"(id) : "memory")

// ---- scratch (device globals: allocation-free rule) ----
__device__ __align__(128) float g_fused[TB * FF];
__device__ __align__(128) float g_X[TB * HH];
// g_Xh/g_Xl: first hold split X for pregemm; after the scan they hold split h (dec A)
__device__ __align__(128) __nv_bfloat16 g_Xh[(size_t)NCH * TB * 32];
__device__ __align__(128) __nv_bfloat16 g_Xl[(size_t)NCH * TB * 32];
__device__ __align__(128) __nv_bfloat16 g_Wh[(size_t)NCH * G4 * 32];
__device__ __align__(128) __nv_bfloat16 g_Wl[(size_t)NCH * G4 * 32];
__device__ __align__(128) __nv_bfloat16 g_U2h[(size_t)NC64 * G4 * 64];
__device__ __align__(128) __nv_bfloat16 g_U2l[(size_t)NC64 * G4 * 64];
__device__ __align__(128) __nv_bfloat16 g_Dh[(size_t)NCH * SS * 32];   // decW hi
__device__ __align__(128) __nv_bfloat16 g_Dl[(size_t)NCH * SS * 32];   // decW lo
__device__ __align__(128) float g_bsum[G4];
__device__ __align__(128) float g_preg[(size_t)TB * G4];
__device__ __align__(128) float g_cT[HH * BB];
__device__ __align__(128) float g_hall[(size_t)TT * HH * BB];
__device__ __align__(128) __nv_bfloat16 g_hsp[2][NC64][2][32][64];
__device__ volatile int g_bar;   // persistent-scan grid barrier (zeroed each launch)

// ---------------- init: c transposed, h0 split, barrier reset ----------------
__global__ void k_init(const float* __restrict__ h0, const float* __restrict__ c0) {
    int i = blockIdx.x * blockDim.x + threadIdx.x;
    if (i == 0) g_bar = 0;
    if (i < HH * BB) {
        int b = i >> 11, u = i & 2047;
        g_cT[u * BB + b] = c0[i];
        float x = h0[i];
        __nv_bfloat16 h = __float2bfloat16(x);
        __nv_bfloat16 l = __float2bfloat16(x - __bfloat162float(h));
        g_hsp[0][u >> 6][0][b][u & 63] = h;
        g_hsp[0][u >> 6][1][b][u & 63] = l;
    }
}

// ---------------- fused = [x1@m1^T+b1 , x2@m2^T+b2] ----------------
__global__ void k_fused(const float* __restrict__ in1, const float* __restrict__ in2,
                        const float* __restrict__ m1W, const float* __restrict__ m1b,
                        const float* __restrict__ m2W, const float* __restrict__ m2b) {
    int idx = blockIdx.x * blockDim.x + threadIdx.x;
    if (idx >= TB) return;
    int t = idx / BB, b = idx % BB;
    float x0 = in1[(b * TT + t) * 2 + 0];
    float x1 = in1[(b * TT + t) * 2 + 1];
    float x2 = in2[b * TT + t];
#pragma unroll
    for (int j = 0; j < 10; j++)
        g_fused[idx * FF + j] = m1W[j * 2] * x0 + m1W[j * 2 + 1] * x1 + m1b[j];
#pragma unroll
    for (int j = 0; j < 10; j++)
        g_fused[idx * FF + 10 + j] = m2W[j] * x2 + m2b[j];
}

// ---------------- expert encode ----------------
__global__ __launch_bounds__(256) void k_encode(const float* __restrict__ encW,
                                                const float* __restrict__ encb,
                                                const int* __restrict__ routers) {
    int idx = blockIdx.x;
    int t = idx / BB, b = idx % BB;
    int skill = routers[b * TT + t];
    __shared__ float sf[FF];
    if (threadIdx.x < FF) sf[threadIdx.x] = g_fused[idx * FF + threadIdx.x];
    __syncthreads();
    const float* Wbase = encW + (size_t)skill * FF * HH;
    const float* bbase = encb + skill * HH;
    for (int h = threadIdx.x; h < HH; h += 256) {
        float acc = bbase[h];
#pragma unroll
        for (int f = 0; f < FF; f++) acc += sf[f] * Wbase[f * HH + h];
        g_X[idx * HH + h] = acc;
    }
}

// ---------------- split X into chunk32-major bf16 hi/lo ----------------
__global__ __launch_bounds__(256) void k_splitX() {
    int m = blockIdx.x * 256 + threadIdx.x;
    int ch = blockIdx.y;
    const float* src = &g_X[(size_t)m * HH + ch * 32];
    union { __nv_bfloat16 b[32]; uint4 v[4]; } ph, pl;
#pragma unroll
    for (int i = 0; i < 32; i++) {
        float x = src[i];
        __nv_bfloat16 h = __float2bfloat16(x);
        ph.b[i] = h;
        pl.b[i] = __float2bfloat16(x - __bfloat162float(h));
    }
    size_t o = ((size_t)ch * TB + m) * 32;
#pragma unroll
    for (int i = 0; i < 4; i++) {
        *(uint4*)&g_Xh[o + i * 8] = ph.v[i];
        *(uint4*)&g_Xl[o + i * 8] = pl.v[i];
    }
}

// ---------------- split Wih into chunk32-major hi/lo + bias ----------------
__global__ __launch_bounds__(256) void k_splitW(const float* __restrict__ W,
                                                __nv_bfloat16* __restrict__ dh,
                                                __nv_bfloat16* __restrict__ dl,
                                                const float* __restrict__ b1,
                                                const float* __restrict__ b2,
                                                int do_bias) {
    int c = blockIdx.x * 256 + threadIdx.x;
    int ch = blockIdx.y;
    int j = (c & 3) * HH + (c >> 2);
    if (do_bias && ch == 0) g_bsum[c] = b1[j] + b2[j];
    const float* src = &W[(size_t)j * HH + ch * 32];
    union { __nv_bfloat16 b[32]; uint4 v[4]; } ph, pl;
#pragma unroll
    for (int i = 0; i < 32; i++) {
        float x = src[i];
        __nv_bfloat16 h = __float2bfloat16(x);
        ph.b[i] = h;
        pl.b[i] = __float2bfloat16(x - __bfloat162float(h));
    }
    size_t o = ((size_t)ch * G4 + c) * 32;
#pragma unroll
    for (int i = 0; i < 4; i++) {
        *(uint4*)&dh[o + i * 8] = ph.v[i];
        *(uint4*)&dl[o + i * 8] = pl.v[i];
    }
}

// ---------------- split decW (no interleave) into chunk32-major hi/lo ----------------
__global__ __launch_bounds__(256) void k_splitD(const float* __restrict__ W) {
    int s = threadIdx.x;
    int ch = blockIdx.y;
    const float* src = &W[(size_t)s * HH + ch * 32];
    union { __nv_bfloat16 b[32]; uint4 v[4]; } ph, pl;
#pragma unroll
    for (int i = 0; i < 32; i++) {
        float x = src[i];
        __nv_bfloat16 h = __float2bfloat16(x);
        ph.b[i] = h;
        pl.b[i] = __float2bfloat16(x - __bfloat162float(h));
    }
    size_t o = ((size_t)ch * SS + s) * 32;
#pragma unroll
    for (int i = 0; i < 4; i++) {
        *(uint4*)&g_Dh[o + i * 8] = ph.v[i];
        *(uint4*)&g_Dl[o + i * 8] = pl.v[i];
    }
}

// ---------------- split Whh into chunk64-major hi/lo ----------------
__global__ __launch_bounds__(256) void k_splitW64(const float* __restrict__ W) {
    int c = blockIdx.x * 256 + threadIdx.x;
    int ch = blockIdx.y;
    int j = (c & 3) * HH + (c >> 2);
    const float* src = &W[(size_t)j * HH + ch * 64];
    union { __nv_bfloat16 b[64]; uint4 v[8]; } ph, pl;
#pragma unroll
    for (int i = 0; i < 64; i++) {
        float x = src[i];
        __nv_bfloat16 h = __float2bfloat16(x);
        ph.b[i] = h;
        pl.b[i] = __float2bfloat16(x - __bfloat162float(h));
    }
    size_t o = ((size_t)ch * G4 + c) * 64;
#pragma unroll
    for (int i = 0; i < 8; i++) {
        *(uint4*)&g_U2h[o + i * 8] = ph.v[i];
        *(uint4*)&g_U2l[o + i * 8] = pl.v[i];
    }
}

// ---------------- HMMA pregemm v3: 256x128 CTA tile, 3-stage prefetch-before-compute ----------------
__global__ __launch_bounds__(256, 1) void k_hmma() {
    extern __shared__ char dsm[];   // 3 x [Ah 16K | Al 16K | Bh 8K | Bl 8K] = 144KB
    __shared__ float sbias[128];
    int tid = threadIdx.x, wid = tid >> 5, lane = tid & 31;
    int wm = wid & 3, wn = wid >> 2;
    int m0 = blockIdx.y * 256, n0 = blockIdx.x * 128;
    uint32_t sb = smem_u32(dsm);
    if (tid < 128) sbias[tid] = g_bsum[n0 + tid];

    auto stage = [&](int ch, int buf) {
        uint32_t tb = sb + buf * 49152;
        const char* sAh = (const char*)g_Xh + ((size_t)ch * TB + m0) * 64;
        const char* sAl = (const char*)g_Xl + ((size_t)ch * TB + m0) * 64;
        const char* sBh = (const char*)g_Wh + ((size_t)ch * G4 + n0) * 64;
        const char* sBl = (const char*)g_Wl + ((size_t)ch * G4 + n0) * 64;
#pragma unroll
        for (int i = 0; i < 4; i++) {
            uint32_t off = (uint32_t)(tid + i * 256) * 16;   // 0..16383
            uint32_t so = sw64(off);
            cpa16s(tb + so,         sAh + off);
            cpa16s(tb + 16384 + so, sAl + off);
        }
#pragma unroll
        for (int i = 0; i < 2; i++) {
            uint32_t off = (uint32_t)(tid + i * 256) * 16;   // 0..8191
            uint32_t so = sw64(off);
            cpa16s(tb + 32768 + so, sBh + off);
            cpa16s(tb + 40960 + so, sBl + off);
        }
        cp_commit();
    };

    float C[4][8][4] = {};
    stage(0, 0);
    stage(1, 1);
    for (int it = 0; it < NCH; it++) {
        if (it < NCH - 1) { asm volatile("cp.async.wait_group 1;" ::: "memory"); }
        else              { asm volatile("cp.async.wait_group 0;" ::: "memory"); }
        __syncthreads();
        if (it + 2 < NCH) stage(it + 2, (it + 2) % 3);
        int buf = it % 3;
        uint32_t base = sb + buf * 49152;
#pragma unroll
        for (int ks = 0; ks < 2; ks++) {
            uint32_t bh[8][2], bl[8][2];
            uint32_t kbB = ks * 32 + ((lane >> 3) & 1) * 16;
#pragma unroll
            for (int nt = 0; nt < 8; nt++) {
                uint32_t offB = (uint32_t)(wn * 64 + nt * 8 + (lane & 7)) * 64 + kbB;
                ldsm_x2(bh[nt], base + 32768 + sw64(offB));
                ldsm_x2(bl[nt], base + 40960 + sw64(offB));
            }
            uint32_t kbA = ks * 32 + ((lane >> 4) & 1) * 16;
#pragma unroll
            for (int mt = 0; mt < 4; mt++) {
                uint32_t offA = (uint32_t)(wm * 64 + mt * 16 + (lane & 15)) * 64 + kbA;
                uint32_t ah[4], al[4];
                ldsm_x4(ah, base + sw64(offA));
                ldsm_x4(al, base + 16384 + sw64(offA));
#pragma unroll
                for (int nt = 0; nt < 8; nt++) {
                    mma_bf16(C[mt][nt], ah, bh[nt]);
                    mma_bf16(C[mt][nt], ah, bl[nt]);
                    mma_bf16(C[mt][nt], al, bh[nt]);
                }
            }
        }
    }

#pragma unroll
    for (int mt = 0; mt < 4; mt++) {
#pragma unroll
        for (int nt = 0; nt < 8; nt++) {
            int cl = wn * 64 + nt * 8 + (lane & 3) * 2;
            int r0 = m0 + wm * 64 + mt * 16 + (lane >> 2);
            float b0 = sbias[cl], b1v = sbias[cl + 1];
            *(float2*)&g_preg[(size_t)r0 * G4 + n0 + cl] =
                make_float2(C[mt][nt][0] + b0, C[mt][nt][1] + b1v);
            *(float2*)&g_preg[(size_t)(r0 + 8) * G4 + n0 + cl] =
                make_float2(C[mt][nt][2] + b0, C[mt][nt][3] + b1v);
        }
    }
}

// ---------------- persistent scan v3: 4 K-slices, cross-barrier B prefetch ----------------
__global__ __launch_bounds__(512) void k_scan() {
    extern __shared__ char sstep[];   // 4 slices x 2 stages x 24KB = 192KB
    __shared__ float gs[32][65];
    __shared__ float ps[3][32][65];
    int tid = threadIdx.x;
    int slice = tid >> 7;             // 0..3, K range [slice*512, +512)
    int lt = tid & 127;
    int wid = lt >> 5, lane = lt & 31;
    int wm = wid & 1, wn = wid >> 1;
    int u0 = blockIdx.x * 16;
    int c0 = u0 * 4;
    uint32_t sb = smem_u32(sstep) + slice * 49152;
    int chbase = slice * 8;
    int barid = slice + 1;

    auto stA = [&](int ch, int buf, int pin) {
        uint32_t tb = sb + buf * 24576;
        const char* sA = (const char*)&g_hsp[pin][ch][0][0][0];
#pragma unroll
        for (int i = 0; i < 4; i++) {
            uint32_t off = (uint32_t)(lt + i * 128) * 16;   // 0..8191
            cpa16s(tb + (off & 4096) + sw128(off & 4095), sA + off);
        }
    };
    auto stB = [&](int ch, int buf) {
        uint32_t tb = sb + buf * 24576;
        const char* sBh = (const char*)g_U2h + ((size_t)ch * G4 + c0) * 128;
        const char* sBl = (const char*)g_U2l + ((size_t)ch * G4 + c0) * 128;
#pragma unroll
        for (int i = 0; i < 4; i++) {
            uint32_t off = (uint32_t)(lt + i * 128) * 16;   // 0..8191
            uint32_t so = sw128(off);
            cpa16s(tb + 8192 + so,  sBh + off);
            cpa16s(tb + 16384 + so, sBl + off);
        }
    };

    // prologue (matches steady-state pending set: [B0, B1, A0, A1])
    stB(chbase + 0, 0); cp_commit();
    stB(chbase + 1, 1); cp_commit();
    stA(chbase + 0, 0, 0); cp_commit();
    stA(chbase + 1, 1, 0); cp_commit();

    for (int t = 0; t < TT; t++) {
        int p_in = t & 1, p_out = (t + 1) & 1;
        // hoist preg read: no dependence on h -> DRAM latency hidden under the gemm
        int be = tid & 31, ue = tid >> 5;
        float4 pr = *(const float4*)&g_preg[(size_t)(t * BB + be) * G4 + (u0 + ue) * 4];

        float C[4][4] = {};
        for (int it = 0; it < 8; it++) {
            asm volatile("cp.async.wait_group 1;" ::: "memory");
            SLICE_BAR(barid);
            int buf = it & 1;
            uint32_t tb = sb + buf * 24576;
            uint32_t TA_h = tb, TA_l = tb + 4096;
            uint32_t TB_h = tb + 8192, TB_l = tb + 16384;
#pragma unroll
            for (int ks = 0; ks < 4; ks++) {
                uint32_t bh[4][2], bl[4][2];
#pragma unroll
                for (int nt = 0; nt < 4; nt++) {
                    uint32_t offB = (uint32_t)(wn * 32 + nt * 8 + (lane & 7)) * 128
                                  + ks * 32 + ((lane >> 3) & 1) * 16;
                    ldsm_x2(bh[nt], TB_h + sw128(offB));
                    ldsm_x2(bl[nt], TB_l + sw128(offB));
                }
                uint32_t offA = (uint32_t)(wm * 16 + (lane & 15)) * 128
                              + ks * 32 + ((lane >> 4) & 1) * 16;
                uint32_t ah[4], al[4];
                ldsm_x4(ah, TA_h + sw128(offA));
                ldsm_x4(al, TA_l + sw128(offA));
#pragma unroll
                for (int nt = 0; nt < 4; nt++) {
                    mma_bf16(C[nt], ah, bh[nt]);
                    mma_bf16(C[nt], ah, bl[nt]);
                    mma_bf16(C[nt], al, bh[nt]);
                }
            }
            SLICE_BAR(barid);
            if (it + 2 < 8) {
                stA(chbase + it + 2, buf, p_in);
                stB(chbase + it + 2, buf);
                cp_commit();
            } else if (it == 6) {
                stB(chbase + 0, 0); cp_commit();   // next step's B0 (step-invariant)
            } else {
                stB(chbase + 1, 1); cp_commit();   // next step's B1
            }
        }

        // cross-slice reduction via smem
        __syncthreads();
        if (slice != 0) {
            float (*pp)[65] = ps[slice - 1];
#pragma unroll
            for (int nt = 0; nt < 4; nt++) {
                int b0 = wm * 16 + (lane >> 2);
                int cl = wn * 32 + nt * 8 + (lane & 3) * 2;
                pp[b0][cl] = C[nt][0];     pp[b0][cl + 1] = C[nt][1];
                pp[b0 + 8][cl] = C[nt][2]; pp[b0 + 8][cl + 1] = C[nt][3];
            }
        }
        __syncthreads();
        if (slice == 0) {
#pragma unroll
            for (int nt = 0; nt < 4; nt++) {
                int b0 = wm * 16 + (lane >> 2);
                int cl = wn * 32 + nt * 8 + (lane & 3) * 2;
                gs[b0][cl]         = C[nt][0] + ps[0][b0][cl] + ps[1][b0][cl] + ps[2][b0][cl];
                gs[b0][cl + 1]     = C[nt][1] + ps[0][b0][cl + 1] + ps[1][b0][cl + 1] + ps[2][b0][cl + 1];
                gs[b0 + 8][cl]     = C[nt][2] + ps[0][b0 + 8][cl] + ps[1][b0 + 8][cl] + ps[2][b0 + 8][cl];
                gs[b0 + 8][cl + 1] = C[nt][3] + ps[0][b0 + 8][cl + 1] + ps[1][b0 + 8][cl + 1] + ps[2][b0 + 8][cl + 1];
            }
        }
        __syncthreads();

        // LSTM elementwise: 512 (b,u) pairs, 1 per thread
        {
            float* __restrict__ hout = &g_hall[(size_t)t * HH * BB];
            int b = be, uu = ue;
            float gi = pr.x + gs[b][uu * 4 + 0];
            float gf = pr.y + gs[b][uu * 4 + 1];
            float gg = pr.z + gs[b][uu * 4 + 2];
            float go = pr.w + gs[b][uu * 4 + 3];
            float si = 1.0f / (1.0f + expf(-gi));
            float sf_ = 1.0f / (1.0f + expf(-gf));
            float so = 1.0f / (1.0f + expf(-go));
            float tg = tanhf(gg);
            int u = u0 + uu;
            float c = sf_ * g_cT[u * BB + b] + si * tg;
            float hnew = so * tanhf(c);
            g_cT[u * BB + b] = c;
            hout[u * BB + b] = hnew;
            __nv_bfloat16 hh = __float2bfloat16(hnew);
            __nv_bfloat16 hl = __float2bfloat16(hnew - __bfloat162float(hh));
            g_hsp[p_out][u >> 6][0][b][u & 63] = hh;
            g_hsp[p_out][u >> 6][1][b][u & 63] = hl;
            size_t dm = ((size_t)(u >> 5) * TB + t * BB + b) * 32 + (u & 31);
            g_Xh[dm] = hh;
            g_Xl[dm] = hl;
        }

        if (t + 1 < TT) {
            // grid-wide barrier
            __threadfence();
            __syncthreads();
            if (tid == 0) {
                atomicAdd((int*)&g_bar, 1);
                int target = 128 * (t + 1);
                while (g_bar < target) __nanosleep(32);
            }
            __syncthreads();
            __threadfence();
            // post-barrier: refill A (B already in flight from before the barrier)
            stA(chbase + 0, 0, p_out); cp_commit();
            stA(chbase + 1, 1, p_out); cp_commit();
        }
    }
    asm volatile("cp.async.wait_group 0;" ::: "memory");
}

// ---------------- HMMA decoder: out = split3(H @ decW^T) + decb  [6400 x 256] ----------------
__global__ __launch_bounds__(256) void k_dmma(const float* __restrict__ decb,
                                              float* __restrict__ out) {
    extern __shared__ char dsm[];   // 3 x 32KB
    __shared__ float sbias[128];
    int tid = threadIdx.x, wid = tid >> 5, lane = tid & 31;
    int wm = wid & 1, wn = wid >> 1;
    int m0 = blockIdx.y * 128, n0 = blockIdx.x * 128;
    uint32_t sb = smem_u32(dsm);
    if (tid < 128) sbias[tid] = decb[n0 + tid];

    auto stage = [&](int ch, int buf) {
        uint32_t tb = sb + buf * 32768;
        const char* sAh = (const char*)g_Xh + ((size_t)ch * TB + m0) * 64;
        const char* sAl = (const char*)g_Xl + ((size_t)ch * TB + m0) * 64;
        const char* sBh = (const char*)g_Dh + ((size_t)ch * SS + n0) * 64;
        const char* sBl = (const char*)g_Dl + ((size_t)ch * SS + n0) * 64;
#pragma unroll
        for (int i = 0; i < 2; i++) {
            uint32_t off = (uint32_t)(tid + i * 256) * 16;
            uint32_t so = sw64(off);
            cpa16s(tb + so,         sAh + off);
            cpa16s(tb + 8192 + so,  sAl + off);
            cpa16s(tb + 16384 + so, sBh + off);
            cpa16s(tb + 24576 + so, sBl + off);
        }
        cp_commit();
    };

    float C[4][4][4] = {};
    stage(0, 0);
    stage(1, 1);
    for (int it = 0; it < NCH; it++) {
        if (it < NCH - 1) { asm volatile("cp.async.wait_group 1;" ::: "memory"); }
        else              { asm volatile("cp.async.wait_group 0;" ::: "memory"); }
        __syncthreads();
        if (it + 2 < NCH) stage(it + 2, (it + 2) % 3);
        int buf = it % 3;
        uint32_t TA_h = sb + buf * 32768;
        uint32_t TA_l = TA_h + 8192;
        uint32_t TB_h = TA_h + 16384;
        uint32_t TB_l = TA_h + 24576;
#pragma unroll
        for (int ks = 0; ks < 2; ks++) {
            uint32_t bh[4][2], bl[4][2];
            uint32_t kbB = ks * 32 + ((lane >> 3) & 1) * 16;
#pragma unroll
            for (int nt = 0; nt < 4; nt++) {
                uint32_t offB = (uint32_t)(wn * 32 + nt * 8 + (lane & 7)) * 64 + kbB;
                ldsm_x2(bh[nt], TB_h + sw64(offB));
                ldsm_x2(bl[nt], TB_l + sw64(offB));
            }
            uint32_t kbA = ks * 32 + ((lane >> 4) & 1) * 16;
#pragma unroll
            for (int mt = 0; mt < 4; mt++) {
                uint32_t offA = (uint32_t)(wm * 64 + mt * 16 + (lane & 15)) * 64 + kbA;
                uint32_t ah[4], al[4];
                ldsm_x4(ah, TA_h + sw64(offA));
                ldsm_x4(al, TA_l + sw64(offA));
#pragma unroll
                for (int nt = 0; nt < 4; nt++) {
                    mma_bf16(C[mt][nt], ah, bh[nt]);
                    mma_bf16(C[mt][nt], ah, bl[nt]);
                    mma_bf16(C[mt][nt], al, bh[nt]);
                }
            }
        }
    }

#pragma unroll
    for (int mt = 0; mt < 4; mt++) {
#pragma unroll
        for (int nt = 0; nt < 4; nt++) {
            int cl = wn * 32 + nt * 8 + (lane & 3) * 2;
            int r0 = m0 + wm * 64 + mt * 16 + (lane >> 2);
            float b0 = sbias[cl], b1v = sbias[cl + 1];
            int bb0 = r0 & 31, tt0 = r0 >> 5;
            *(float2*)&out[((size_t)bb0 * TT + tt0) * SS + n0 + cl] =
                make_float2(C[mt][nt][0] + b0, C[mt][nt][1] + b1v);
            int r1 = r0 + 8;
            int bb1 = r1 & 31, tt1 = r1 >> 5;
            *(float2*)&out[((size_t)bb1 * TT + tt1) * SS + n0 + cl] =
                make_float2(C[mt][nt][2] + b0, C[mt][nt][3] + b1v);
        }
    }
}

// ---------------- final state write-out ----------------
__global__ void k_finish(float* __restrict__ out, int out_size) {
    int i = blockIdx.x * blockDim.x + threadIdx.x;
    if (i < HH * BB) {
        int b = i / HH, k = i % HH;
        int base = TB * SS;
        const float* hlast = &g_hall[(size_t)(TT - 1) * HH * BB];
        if (base + i < out_size) out[base + i] = hlast[k * BB + b];
        if (base + HH * BB + i < out_size) out[base + HH * BB + i] = g_cT[k * BB + b];
    }
}

extern "C" void kernel_launch(void* const* d_in, const int* in_sizes, int n_in,
                              void* d_out, int out_size) {
    const float* in1  = (const float*)d_in[0];
    const float* in2  = (const float*)d_in[1];
    const float* h0   = (const float*)d_in[2];
    const float* c0   = (const float*)d_in[3];
    const int*   rt   = (const int*)  d_in[4];
    const float* m1W  = (const float*)d_in[5];
    const float* m1b  = (const float*)d_in[6];
    const float* m2W  = (const float*)d_in[7];
    const float* m2b  = (const float*)d_in[8];
    const float* encW = (const float*)d_in[9];
    const float* encb = (const float*)d_in[10];
    const float* Wih  = (const float*)d_in[11];
    const float* Whh  = (const float*)d_in[12];
    const float* bih  = (const float*)d_in[13];
    const float* bhh  = (const float*)d_in[14];
    const float* decW = (const float*)d_in[15];
    const float* decb = (const float*)d_in[16];
    float* out = (float*)d_out;

    const int HMMA_SMEM = 3 * 49152;       // 144KB
    const int SCAN_SMEM = 4 * 2 * 24576;   // 192KB
    const int DMMA_SMEM = 3 * 32768;       // 96KB

    static int attr_done = 0;
    if (!attr_done) {
        cudaFuncSetAttribute(k_hmma, cudaFuncAttributeMaxDynamicSharedMemorySize, HMMA_SMEM);
        cudaFuncSetAttribute(k_dmma, cudaFuncAttributeMaxDynamicSharedMemorySize, DMMA_SMEM);
        cudaFuncSetAttribute(k_scan, cudaFuncAttributeMaxDynamicSharedMemorySize, SCAN_SMEM);
        attr_done = 1;
    }

    __nv_bfloat16 *wh, *wl;
    cudaGetSymbolAddress((void**)&wh, g_Wh);
    cudaGetSymbolAddress((void**)&wl, g_Wl);

    k_init<<<(HH * BB + 255) / 256, 256>>>(h0, c0);
    k_fused<<<(TB + 127) / 128, 128>>>(in1, in2, m1W, m1b, m2W, m2b);
    k_encode<<<TB, 256>>>(encW, encb, rt);
    k_splitX<<<dim3(TB / 256, NCH), 256>>>();
    k_splitW<<<dim3(G4 / 256, NCH), 256>>>(Wih, wh, wl, bih, bhh, 1);
    k_splitW64<<<dim3(G4 / 256, NC64), 256>>>(Whh);
    k_splitD<<<dim3(1, NCH), 256>>>(decW);
    k_hmma<<<dim3(G4 / 128, TB / 256), 256, HMMA_SMEM>>>();
    k_scan<<<128, 512, SCAN_SMEM>>>();
    k_dmma<<<dim3(SS / 128, TB / 128), 256, DMMA_SMEM>>>(decb, out);
    k_finish<<<(HH * BB + 255) / 256, 256>>>(out, out_size);
}

// round 17
// speedup vs baseline: 1.5981x; 1.0262x over previous
#include <cuda_runtime.h>
#include <cuda_bf16.h>
#include <math.h>
#include <stdint.h>

#define BB 32
#define TT 200
#define HH 2048
#define G4 8192   // 4*H
#define SS 256
#define TB 6400   // T*B
#define FF 20
#define NCH 64    // K chunks of 32 (pregemm/dec)
#define NC64 32   // K chunks of 64 (scan)

typedef unsigned long long ull;

// ---- cp.async ----
__device__ __forceinline__ void cpa16s(uint32_t dst, const void* src) {
    asm volatile("cp.async.cg.shared.global [%0], [%1], 16;" :: "r"(dst), "l"(src));
}
__device__ __forceinline__ void cp_commit() { asm volatile("cp.async.commit_group;"); }

__device__ __forceinline__ uint32_t smem_u32(const void* p) {
    return (uint32_t)__cvta_generic_to_shared(p);
}
__device__ __forceinline__ uint32_t sw64(uint32_t off)  { return off ^ (((off >> 7) & 7u) << 4); }
__device__ __forceinline__ uint32_t sw128(uint32_t off) { return off ^ ((off >> 3) & 0x70u); }

// ---- ldmatrix / mma.sync (baseline PTX, legal on sm_103 non-'a') ----
__device__ __forceinline__ void ldsm_x4(uint32_t* r, uint32_t addr) {
    asm volatile("ldmatrix.sync.aligned.m8n8.x4.shared.b16 {%0,%1,%2,%3}, [%4];"
                 : "=r"(r[0]), "=r"(r[1]), "=r"(r[2]), "=r"(r[3]) : "r"(addr));
}
__device__ __forceinline__ void ldsm_x2(uint32_t* r, uint32_t addr) {
    asm volatile("ldmatrix.sync.aligned.m8n8.x2.shared.b16 {%0,%1}, [%2];"
                 : "=r"(r[0]), "=r"(r[1]) : "r"(addr));
}
__device__ __forceinline__ void mma_bf16(float* c, const uint32_t* a, const uint32_t* b) {
    asm volatile(
        "mma.sync.aligned.m16n8k16.row.col.f32.bf16.bf16.f32 "
        "{%0,%1,%2,%3}, {%4,%5,%6,%7}, {%8,%9}, {%0,%1,%2,%3};"
        : "+f"(c[0]), "+f"(c[1]), "+f"(c[2]), "+f"(c[3])
        : "r"(a[0]), "r"(a[1]), "r"(a[2]), "r"(a[3]), "r"(b[0]), "r"(b[1]));
}
#define SLICE_BAR(id) asm volatile("bar.sync %0, 128;" :: "r"(id) : "memory")

// ---- scratch (device globals: allocation-free rule) ----
__device__ __align__(128) float g_fused[TB * FF];
// g_Xh/g_Xl: first hold split X for pregemm; after the scan they hold split h (dec A)
__device__ __align__(128) __nv_bfloat16 g_Xh[(size_t)NCH * TB * 32];
__device__ __align__(128) __nv_bfloat16 g_Xl[(size_t)NCH * TB * 32];
__device__ __align__(128) __nv_bfloat16 g_Wh[(size_t)NCH * G4 * 32];
__device__ __align__(128) __nv_bfloat16 g_Wl[(size_t)NCH * G4 * 32];
__device__ __align__(128) __nv_bfloat16 g_U2h[(size_t)NC64 * G4 * 64];
__device__ __align__(128) __nv_bfloat16 g_U2l[(size_t)NC64 * G4 * 64];
__device__ __align__(128) __nv_bfloat16 g_Dh[(size_t)NCH * SS * 32];   // decW hi
__device__ __align__(128) __nv_bfloat16 g_Dl[(size_t)NCH * SS * 32];   // decW lo
__device__ __align__(128) float g_bsum[G4];
__device__ __align__(128) float g_preg[(size_t)TB * G4];
__device__ __align__(128) float g_cT[HH * BB];
__device__ __align__(128) float g_hall[(size_t)TT * HH * BB];
__device__ __align__(128) __nv_bfloat16 g_hsp[2][NC64][2][32][64];
__device__ volatile int g_bar;   // persistent-scan grid barrier (zeroed each launch)

// ---------------- init: c transposed, h0 split, barrier reset ----------------
__global__ void k_init(const float* __restrict__ h0, const float* __restrict__ c0) {
    int i = blockIdx.x * blockDim.x + threadIdx.x;
    if (i == 0) g_bar = 0;
    if (i < HH * BB) {
        int b = i >> 11, u = i & 2047;
        g_cT[u * BB + b] = c0[i];
        float x = h0[i];
        __nv_bfloat16 h = __float2bfloat16(x);
        __nv_bfloat16 l = __float2bfloat16(x - __bfloat162float(h));
        g_hsp[0][u >> 6][0][b][u & 63] = h;
        g_hsp[0][u >> 6][1][b][u & 63] = l;
    }
}

// ---------------- fused = [x1@m1^T+b1 , x2@m2^T+b2] ----------------
__global__ void k_fused(const float* __restrict__ in1, const float* __restrict__ in2,
                        const float* __restrict__ m1W, const float* __restrict__ m1b,
                        const float* __restrict__ m2W, const float* __restrict__ m2b) {
    int idx = blockIdx.x * blockDim.x + threadIdx.x;
    if (idx >= TB) return;
    int t = idx / BB, b = idx % BB;
    float x0 = in1[(b * TT + t) * 2 + 0];
    float x1 = in1[(b * TT + t) * 2 + 1];
    float x2 = in2[b * TT + t];
#pragma unroll
    for (int j = 0; j < 10; j++)
        g_fused[idx * FF + j] = m1W[j * 2] * x0 + m1W[j * 2 + 1] * x1 + m1b[j];
#pragma unroll
    for (int j = 0; j < 10; j++)
        g_fused[idx * FF + 10 + j] = m2W[j] * x2 + m2b[j];
}

// ---------------- expert encode fused with bf16 hi/lo chunk-major split ----------------
__global__ __launch_bounds__(256) void k_encode(const float* __restrict__ encW,
                                                const float* __restrict__ encb,
                                                const int* __restrict__ routers) {
    int idx = blockIdx.x;
    int t = idx / BB, b = idx % BB;
    int skill = routers[b * TT + t];
    __shared__ float sf[FF];
    if (threadIdx.x < FF) sf[threadIdx.x] = g_fused[idx * FF + threadIdx.x];
    __syncthreads();
    const float* Wbase = encW + (size_t)skill * FF * HH;
    const float* bbase = encb + skill * HH;
#pragma unroll
    for (int k = 0; k < 8; k++) {
        int h = k * 256 + threadIdx.x;
        float acc = bbase[h];
#pragma unroll
        for (int f = 0; f < FF; f++) acc += sf[f] * Wbase[f * HH + h];
        __nv_bfloat16 hi = __float2bfloat16(acc);
        __nv_bfloat16 lo = __float2bfloat16(acc - __bfloat162float(hi));
        size_t o = ((size_t)(h >> 5) * TB + idx) * 32 + (h & 31);
        g_Xh[o] = hi;
        g_Xl[o] = lo;
    }
}

// ---------------- split Wih into chunk32-major hi/lo + bias ----------------
__global__ __launch_bounds__(256) void k_splitW(const float* __restrict__ W,
                                                __nv_bfloat16* __restrict__ dh,
                                                __nv_bfloat16* __restrict__ dl,
                                                const float* __restrict__ b1,
                                                const float* __restrict__ b2,
                                                int do_bias) {
    int c = blockIdx.x * 256 + threadIdx.x;
    int ch = blockIdx.y;
    int j = (c & 3) * HH + (c >> 2);
    if (do_bias && ch == 0) g_bsum[c] = b1[j] + b2[j];
    const float* src = &W[(size_t)j * HH + ch * 32];
    union { __nv_bfloat16 b[32]; uint4 v[4]; } ph, pl;
#pragma unroll
    for (int i = 0; i < 32; i++) {
        float x = src[i];
        __nv_bfloat16 h = __float2bfloat16(x);
        ph.b[i] = h;
        pl.b[i] = __float2bfloat16(x - __bfloat162float(h));
    }
    size_t o = ((size_t)ch * G4 + c) * 32;
#pragma unroll
    for (int i = 0; i < 4; i++) {
        *(uint4*)&dh[o + i * 8] = ph.v[i];
        *(uint4*)&dl[o + i * 8] = pl.v[i];
    }
}

// ---------------- split decW (no interleave) into chunk32-major hi/lo ----------------
__global__ __launch_bounds__(256) void k_splitD(const float* __restrict__ W) {
    int s = threadIdx.x;
    int ch = blockIdx.y;
    const float* src = &W[(size_t)s * HH + ch * 32];
    union { __nv_bfloat16 b[32]; uint4 v[4]; } ph, pl;
#pragma unroll
    for (int i = 0; i < 32; i++) {
        float x = src[i];
        __nv_bfloat16 h = __float2bfloat16(x);
        ph.b[i] = h;
        pl.b[i] = __float2bfloat16(x - __bfloat162float(h));
    }
    size_t o = ((size_t)ch * SS + s) * 32;
#pragma unroll
    for (int i = 0; i < 4; i++) {
        *(uint4*)&g_Dh[o + i * 8] = ph.v[i];
        *(uint4*)&g_Dl[o + i * 8] = pl.v[i];
    }
}

// ---------------- split Whh into chunk64-major hi/lo ----------------
__global__ __launch_bounds__(256) void k_splitW64(const float* __restrict__ W) {
    int c = blockIdx.x * 256 + threadIdx.x;
    int ch = blockIdx.y;
    int j = (c & 3) * HH + (c >> 2);
    const float* src = &W[(size_t)j * HH + ch * 64];
    union { __nv_bfloat16 b[64]; uint4 v[8]; } ph, pl;
#pragma unroll
    for (int i = 0; i < 64; i++) {
        float x = src[i];
        __nv_bfloat16 h = __float2bfloat16(x);
        ph.b[i] = h;
        pl.b[i] = __float2bfloat16(x - __bfloat162float(h));
    }
    size_t o = ((size_t)ch * G4 + c) * 64;
#pragma unroll
    for (int i = 0; i < 8; i++) {
        *(uint4*)&g_U2h[o + i * 8] = ph.v[i];
        *(uint4*)&g_U2l[o + i * 8] = pl.v[i];
    }
}

// ---------------- HMMA pregemm: 256x128 CTA tile, 3-stage prefetch-before-compute ----------------
__global__ __launch_bounds__(256, 1) void k_hmma() {
    extern __shared__ char dsm[];   // 3 x [Ah 16K | Al 16K | Bh 8K | Bl 8K] = 144KB
    __shared__ float sbias[128];
    int tid = threadIdx.x, wid = tid >> 5, lane = tid & 31;
    int wm = wid & 3, wn = wid >> 2;
    int m0 = blockIdx.y * 256, n0 = blockIdx.x * 128;
    uint32_t sb = smem_u32(dsm);
    if (tid < 128) sbias[tid] = g_bsum[n0 + tid];

    auto stage = [&](int ch, int buf) {
        uint32_t tb = sb + buf * 49152;
        const char* sAh = (const char*)g_Xh + ((size_t)ch * TB + m0) * 64;
        const char* sAl = (const char*)g_Xl + ((size_t)ch * TB + m0) * 64;
        const char* sBh = (const char*)g_Wh + ((size_t)ch * G4 + n0) * 64;
        const char* sBl = (const char*)g_Wl + ((size_t)ch * G4 + n0) * 64;
#pragma unroll
        for (int i = 0; i < 4; i++) {
            uint32_t off = (uint32_t)(tid + i * 256) * 16;   // 0..16383
            uint32_t so = sw64(off);
            cpa16s(tb + so,         sAh + off);
            cpa16s(tb + 16384 + so, sAl + off);
        }
#pragma unroll
        for (int i = 0; i < 2; i++) {
            uint32_t off = (uint32_t)(tid + i * 256) * 16;   // 0..8191
            uint32_t so = sw64(off);
            cpa16s(tb + 32768 + so, sBh + off);
            cpa16s(tb + 40960 + so, sBl + off);
        }
        cp_commit();
    };

    float C[4][8][4] = {};
    stage(0, 0);
    stage(1, 1);
    for (int it = 0; it < NCH; it++) {
        if (it < NCH - 1) { asm volatile("cp.async.wait_group 1;" ::: "memory"); }
        else              { asm volatile("cp.async.wait_group 0;" ::: "memory"); }
        __syncthreads();
        if (it + 2 < NCH) stage(it + 2, (it + 2) % 3);
        int buf = it % 3;
        uint32_t base = sb + buf * 49152;
#pragma unroll
        for (int ks = 0; ks < 2; ks++) {
            uint32_t bh[8][2], bl[8][2];
            uint32_t kbB = ks * 32 + ((lane >> 3) & 1) * 16;
#pragma unroll
            for (int nt = 0; nt < 8; nt++) {
                uint32_t offB = (uint32_t)(wn * 64 + nt * 8 + (lane & 7)) * 64 + kbB;
                ldsm_x2(bh[nt], base + 32768 + sw64(offB));
                ldsm_x2(bl[nt], base + 40960 + sw64(offB));
            }
            uint32_t kbA = ks * 32 + ((lane >> 4) & 1) * 16;
#pragma unroll
            for (int mt = 0; mt < 4; mt++) {
                uint32_t offA = (uint32_t)(wm * 64 + mt * 16 + (lane & 15)) * 64 + kbA;
                uint32_t ah[4], al[4];
                ldsm_x4(ah, base + sw64(offA));
                ldsm_x4(al, base + 16384 + sw64(offA));
#pragma unroll
                for (int nt = 0; nt < 8; nt++) {
                    mma_bf16(C[mt][nt], ah, bh[nt]);
                    mma_bf16(C[mt][nt], ah, bl[nt]);
                    mma_bf16(C[mt][nt], al, bh[nt]);
                }
            }
        }
    }

#pragma unroll
    for (int mt = 0; mt < 4; mt++) {
#pragma unroll
        for (int nt = 0; nt < 8; nt++) {
            int cl = wn * 64 + nt * 8 + (lane & 3) * 2;
            int r0 = m0 + wm * 64 + mt * 16 + (lane >> 2);
            float b0 = sbias[cl], b1v = sbias[cl + 1];
            *(float2*)&g_preg[(size_t)r0 * G4 + n0 + cl] =
                make_float2(C[mt][nt][0] + b0, C[mt][nt][1] + b1v);
            *(float2*)&g_preg[(size_t)(r0 + 8) * G4 + n0 + cl] =
                make_float2(C[mt][nt][2] + b0, C[mt][nt][3] + b1v);
        }
    }
}

// ---------------- persistent scan v4: 4 K-slices, B prefetch, 1-sync epilogue ----------------
__global__ __launch_bounds__(512) void k_scan() {
    extern __shared__ char sstep[];   // 4 slices x 2 stages x 24KB = 192KB
    __shared__ float ps[4][32][65];
    int tid = threadIdx.x;
    int slice = tid >> 7;             // 0..3, K range [slice*512, +512)
    int lt = tid & 127;
    int wid = lt >> 5, lane = lt & 31;
    int wm = wid & 1, wn = wid >> 1;
    int u0 = blockIdx.x * 16;
    int c0 = u0 * 4;
    uint32_t sb = smem_u32(sstep) + slice * 49152;
    int chbase = slice * 8;
    int barid = slice + 1;

    auto stA = [&](int ch, int buf, int pin) {
        uint32_t tb = sb + buf * 24576;
        const char* sA = (const char*)&g_hsp[pin][ch][0][0][0];
#pragma unroll
        for (int i = 0; i < 4; i++) {
            uint32_t off = (uint32_t)(lt + i * 128) * 16;   // 0..8191
            cpa16s(tb + (off & 4096) + sw128(off & 4095), sA + off);
        }
    };
    auto stB = [&](int ch, int buf) {
        uint32_t tb = sb + buf * 24576;
        const char* sBh = (const char*)g_U2h + ((size_t)ch * G4 + c0) * 128;
        const char* sBl = (const char*)g_U2l + ((size_t)ch * G4 + c0) * 128;
#pragma unroll
        for (int i = 0; i < 4; i++) {
            uint32_t off = (uint32_t)(lt + i * 128) * 16;   // 0..8191
            uint32_t so = sw128(off);
            cpa16s(tb + 8192 + so,  sBh + off);
            cpa16s(tb + 16384 + so, sBl + off);
        }
    };

    // prologue (matches steady-state pending set: [B0, B1, A0, A1])
    stB(chbase + 0, 0); cp_commit();
    stB(chbase + 1, 1); cp_commit();
    stA(chbase + 0, 0, 0); cp_commit();
    stA(chbase + 1, 1, 0); cp_commit();

    for (int t = 0; t < TT; t++) {
        int p_in = t & 1, p_out = (t + 1) & 1;
        int be = tid & 31, ue = tid >> 5;
        float4 pr = *(const float4*)&g_preg[(size_t)(t * BB + be) * G4 + (u0 + ue) * 4];

        float C[4][4] = {};
        for (int it = 0; it < 8; it++) {
            asm volatile("cp.async.wait_group 1;" ::: "memory");
            SLICE_BAR(barid);
            int buf = it & 1;
            uint32_t tb = sb + buf * 24576;
            uint32_t TA_h = tb, TA_l = tb + 4096;
            uint32_t TB_h = tb + 8192, TB_l = tb + 16384;
#pragma unroll
            for (int ks = 0; ks < 4; ks++) {
                uint32_t bh[4][2], bl[4][2];
#pragma unroll
                for (int nt = 0; nt < 4; nt++) {
                    uint32_t offB = (uint32_t)(wn * 32 + nt * 8 + (lane & 7)) * 128
                                  + ks * 32 + ((lane >> 3) & 1) * 16;
                    ldsm_x2(bh[nt], TB_h + sw128(offB));
                    ldsm_x2(bl[nt], TB_l + sw128(offB));
                }
                uint32_t offA = (uint32_t)(wm * 16 + (lane & 15)) * 128
                              + ks * 32 + ((lane >> 4) & 1) * 16;
                uint32_t ah[4], al[4];
                ldsm_x4(ah, TA_h + sw128(offA));
                ldsm_x4(al, TA_l + sw128(offA));
#pragma unroll
                for (int nt = 0; nt < 4; nt++) {
                    mma_bf16(C[nt], ah, bh[nt]);
                    mma_bf16(C[nt], ah, bl[nt]);
                    mma_bf16(C[nt], al, bh[nt]);
                }
            }
            SLICE_BAR(barid);
            if (it + 2 < 8) {
                stA(chbase + it + 2, buf, p_in);
                stB(chbase + it + 2, buf);
                cp_commit();
            } else if (it == 6) {
                stB(chbase + 0, 0); cp_commit();   // next step's B0 (step-invariant)
            } else {
                stB(chbase + 1, 1); cp_commit();   // next step's B1
            }
        }

        // all slices publish partials; single sync; elementwise sums 4-way directly
        {
            float (*pp)[65] = ps[slice];
#pragma unroll
            for (int nt = 0; nt < 4; nt++) {
                int b0 = wm * 16 + (lane >> 2);
                int cl = wn * 32 + nt * 8 + (lane & 3) * 2;
                pp[b0][cl] = C[nt][0];     pp[b0][cl + 1] = C[nt][1];
                pp[b0 + 8][cl] = C[nt][2]; pp[b0 + 8][cl + 1] = C[nt][3];
            }
        }
        __syncthreads();

        // LSTM elementwise: 512 (b,u) pairs, 1 per thread
        {
            float* __restrict__ hout = &g_hall[(size_t)t * HH * BB];
            int b = be, uu = ue;
            int cb = uu * 4;
            float gi = pr.x + ps[0][b][cb + 0] + ps[1][b][cb + 0] + ps[2][b][cb + 0] + ps[3][b][cb + 0];
            float gf = pr.y + ps[0][b][cb + 1] + ps[1][b][cb + 1] + ps[2][b][cb + 1] + ps[3][b][cb + 1];
            float gg = pr.z + ps[0][b][cb + 2] + ps[1][b][cb + 2] + ps[2][b][cb + 2] + ps[3][b][cb + 2];
            float go = pr.w + ps[0][b][cb + 3] + ps[1][b][cb + 3] + ps[2][b][cb + 3] + ps[3][b][cb + 3];
            float si = 1.0f / (1.0f + expf(-gi));
            float sf_ = 1.0f / (1.0f + expf(-gf));
            float so = 1.0f / (1.0f + expf(-go));
            float tg = tanhf(gg);
            int u = u0 + uu;
            float c = sf_ * g_cT[u * BB + b] + si * tg;
            float hnew = so * tanhf(c);
            g_cT[u * BB + b] = c;
            hout[u * BB + b] = hnew;
            __nv_bfloat16 hh = __float2bfloat16(hnew);
            __nv_bfloat16 hl = __float2bfloat16(hnew - __bfloat162float(hh));
            g_hsp[p_out][u >> 6][0][b][u & 63] = hh;
            g_hsp[p_out][u >> 6][1][b][u & 63] = hl;
            size_t dm = ((size_t)(u >> 5) * TB + t * BB + b) * 32 + (u & 31);
            g_Xh[dm] = hh;
            g_Xl[dm] = hl;
        }

        if (t + 1 < TT) {
            // grid-wide barrier
            __threadfence();
            __syncthreads();
            if (tid == 0) {
                atomicAdd((int*)&g_bar, 1);
                int target = 128 * (t + 1);
                while (g_bar < target) __nanosleep(32);
            }
            __syncthreads();
            __threadfence();
            // post-barrier: refill A (B already in flight from before the barrier)
            stA(chbase + 0, 0, p_out); cp_commit();
            stA(chbase + 1, 1, p_out); cp_commit();
        }
    }
    asm volatile("cp.async.wait_group 0;" ::: "memory");
}

// ---------------- HMMA decoder: out = split3(H @ decW^T) + decb  [6400 x 256] ----------------
__global__ __launch_bounds__(256) void k_dmma(const float* __restrict__ decb,
                                              float* __restrict__ out) {
    extern __shared__ char dsm[];   // 3 x 32KB
    __shared__ float sbias[128];
    int tid = threadIdx.x, wid = tid >> 5, lane = tid & 31;
    int wm = wid & 1, wn = wid >> 1;
    int m0 = blockIdx.y * 128, n0 = blockIdx.x * 128;
    uint32_t sb = smem_u32(dsm);
    if (tid < 128) sbias[tid] = decb[n0 + tid];

    auto stage = [&](int ch, int buf) {
        uint32_t tb = sb + buf * 32768;
        const char* sAh = (const char*)g_Xh + ((size_t)ch * TB + m0) * 64;
        const char* sAl = (const char*)g_Xl + ((size_t)ch * TB + m0) * 64;
        const char* sBh = (const char*)g_Dh + ((size_t)ch * SS + n0) * 64;
        const char* sBl = (const char*)g_Dl + ((size_t)ch * SS + n0) * 64;
#pragma unroll
        for (int i = 0; i < 2; i++) {
            uint32_t off = (uint32_t)(tid + i * 256) * 16;
            uint32_t so = sw64(off);
            cpa16s(tb + so,         sAh + off);
            cpa16s(tb + 8192 + so,  sAl + off);
            cpa16s(tb + 16384 + so, sBh + off);
            cpa16s(tb + 24576 + so, sBl + off);
        }
        cp_commit();
    };

    float C[4][4][4] = {};
    stage(0, 0);
    stage(1, 1);
    for (int it = 0; it < NCH; it++) {
        if (it < NCH - 1) { asm volatile("cp.async.wait_group 1;" ::: "memory"); }
        else              { asm volatile("cp.async.wait_group 0;" ::: "memory"); }
        __syncthreads();
        if (it + 2 < NCH) stage(it + 2, (it + 2) % 3);
        int buf = it % 3;
        uint32_t TA_h = sb + buf * 32768;
        uint32_t TA_l = TA_h + 8192;
        uint32_t TB_h = TA_h + 16384;
        uint32_t TB_l = TA_h + 24576;
#pragma unroll
        for (int ks = 0; ks < 2; ks++) {
            uint32_t bh[4][2], bl[4][2];
            uint32_t kbB = ks * 32 + ((lane >> 3) & 1) * 16;
#pragma unroll
            for (int nt = 0; nt < 4; nt++) {
                uint32_t offB = (uint32_t)(wn * 32 + nt * 8 + (lane & 7)) * 64 + kbB;
                ldsm_x2(bh[nt], TB_h + sw64(offB));
                ldsm_x2(bl[nt], TB_l + sw64(offB));
            }
            uint32_t kbA = ks * 32 + ((lane >> 4) & 1) * 16;
#pragma unroll
            for (int mt = 0; mt < 4; mt++) {
                uint32_t offA = (uint32_t)(wm * 64 + mt * 16 + (lane & 15)) * 64 + kbA;
                uint32_t ah[4], al[4];
                ldsm_x4(ah, TA_h + sw64(offA));
                ldsm_x4(al, TA_l + sw64(offA));
#pragma unroll
                for (int nt = 0; nt < 4; nt++) {
                    mma_bf16(C[mt][nt], ah, bh[nt]);
                    mma_bf16(C[mt][nt], ah, bl[nt]);
                    mma_bf16(C[mt][nt], al, bh[nt]);
                }
            }
        }
    }

#pragma unroll
    for (int mt = 0; mt < 4; mt++) {
#pragma unroll
        for (int nt = 0; nt < 4; nt++) {
            int cl = wn * 32 + nt * 8 + (lane & 3) * 2;
            int r0 = m0 + wm * 64 + mt * 16 + (lane >> 2);
            float b0 = sbias[cl], b1v = sbias[cl + 1];
            int bb0 = r0 & 31, tt0 = r0 >> 5;
            *(float2*)&out[((size_t)bb0 * TT + tt0) * SS + n0 + cl] =
                make_float2(C[mt][nt][0] + b0, C[mt][nt][1] + b1v);
            int r1 = r0 + 8;
            int bb1 = r1 & 31, tt1 = r1 >> 5;
            *(float2*)&out[((size_t)bb1 * TT + tt1) * SS + n0 + cl] =
                make_float2(C[mt][nt][2] + b0, C[mt][nt][3] + b1v);
        }
    }
}

// ---------------- final state write-out ----------------
__global__ void k_finish(float* __restrict__ out, int out_size) {
    int i = blockIdx.x * blockDim.x + threadIdx.x;
    if (i < HH * BB) {
        int b = i / HH, k = i % HH;
        int base = TB * SS;
        const float* hlast = &g_hall[(size_t)(TT - 1) * HH * BB];
        if (base + i < out_size) out[base + i] = hlast[k * BB + b];
        if (base + HH * BB + i < out_size) out[base + HH * BB + i] = g_cT[k * BB + b];
    }
}

extern "C" void kernel_launch(void* const* d_in, const int* in_sizes, int n_in,
                              void* d_out, int out_size) {
    const float* in1  = (const float*)d_in[0];
    const float* in2  = (const float*)d_in[1];
    const float* h0   = (const float*)d_in[2];
    const float* c0   = (const float*)d_in[3];
    const int*   rt   = (const int*)  d_in[4];
    const float* m1W  = (const float*)d_in[5];
    const float* m1b  = (const float*)d_in[6];
    const float* m2W  = (const float*)d_in[7];
    const float* m2b  = (const float*)d_in[8];
    const float* encW = (const float*)d_in[9];
    const float* encb = (const float*)d_in[10];
    const float* Wih  = (const float*)d_in[11];
    const float* Whh  = (const float*)d_in[12];
    const float* bih  = (const float*)d_in[13];
    const float* bhh  = (const float*)d_in[14];
    const float* decW = (const float*)d_in[15];
    const float* decb = (const float*)d_in[16];
    float* out = (float*)d_out;

    const int HMMA_SMEM = 3 * 49152;       // 144KB
    const int SCAN_SMEM = 4 * 2 * 24576;   // 192KB
    const int DMMA_SMEM = 3 * 32768;       // 96KB

    static int attr_done = 0;
    if (!attr_done) {
        cudaFuncSetAttribute(k_hmma, cudaFuncAttributeMaxDynamicSharedMemorySize, HMMA_SMEM);
        cudaFuncSetAttribute(k_dmma, cudaFuncAttributeMaxDynamicSharedMemorySize, DMMA_SMEM);
        cudaFuncSetAttribute(k_scan, cudaFuncAttributeMaxDynamicSharedMemorySize, SCAN_SMEM);
        attr_done = 1;
    }

    __nv_bfloat16 *wh, *wl;
    cudaGetSymbolAddress((void**)&wh, g_Wh);
    cudaGetSymbolAddress((void**)&wl, g_Wl);

    k_init<<<(HH * BB + 255) / 256, 256>>>(h0, c0);
    k_fused<<<(TB + 127) / 128, 128>>>(in1, in2, m1W, m1b, m2W, m2b);
    k_encode<<<TB, 256>>>(encW, encb, rt);
    k_splitW<<<dim3(G4 / 256, NCH), 256>>>(Wih, wh, wl, bih, bhh, 1);
    k_splitW64<<<dim3(G4 / 256, NC64), 256>>>(Whh);
    k_splitD<<<dim3(1, NCH), 256>>>(decW);
    k_hmma<<<dim3(G4 / 128, TB / 256), 256, HMMA_SMEM>>>();
    k_scan<<<128, 512, SCAN_SMEM>>>();
    k_dmma<<<dim3(SS / 128, TB / 128), 256, DMMA_SMEM>>>(decb, out);
    k_finish<<<(HH * BB + 255) / 256, 256>>>(out, out_size);
}